// round 2
// baseline (speedup 1.0000x reference)
#include <cuda_runtime.h>
#include <cuda_bf16.h>

#define B_   4
#define L_   1024
#define D_   1024
#define H_   16
#define HD_  64
#define M_TOT (B_ * L_)   // 4096

// Scratch (static device globals — allocation-guard safe)
__device__ float g_Qp[M_TOT * D_];
__device__ float g_Kp[M_TOT * D_];
__device__ float g_Vp[M_TOT * D_];
__device__ float g_At[M_TOT * D_];

// ---------------------------------------------------------------------------
// GEMM: C[M,N] = A[M,K] @ W[N,K]^T + bias[N]
// 64x64 tile, BK=32, 256 threads, 4x4 microtile per thread.
// ---------------------------------------------------------------------------
__global__ __launch_bounds__(256) void gemm_bias_kernel(
    const float* __restrict__ A, const float* __restrict__ W,
    const float* __restrict__ bias, float* __restrict__ C,
    int M, int N, int K)
{
    __shared__ float As[64][33];
    __shared__ float Bs[64][33];

    const int t  = threadIdx.x;
    const int tx = t & 15;
    const int ty = t >> 4;
    const int m0 = blockIdx.y * 64;
    const int n0 = blockIdx.x * 64;

    float acc[4][4] = {};

    for (int k0 = 0; k0 < K; k0 += 32) {
        #pragma unroll
        for (int s = 0; s < 2; s++) {
            int v = t + s * 256;          // 512 float4 per operand tile
            int r = v >> 3;
            int c = (v & 7) << 2;
            float4 a = *reinterpret_cast<const float4*>(A + (size_t)(m0 + r) * K + k0 + c);
            As[r][c + 0] = a.x; As[r][c + 1] = a.y; As[r][c + 2] = a.z; As[r][c + 3] = a.w;
            float4 w = *reinterpret_cast<const float4*>(W + (size_t)(n0 + r) * K + k0 + c);
            Bs[r][c + 0] = w.x; Bs[r][c + 1] = w.y; Bs[r][c + 2] = w.z; Bs[r][c + 3] = w.w;
        }
        __syncthreads();

        #pragma unroll
        for (int kk = 0; kk < 32; kk++) {
            float a[4], b[4];
            #pragma unroll
            for (int i = 0; i < 4; i++) a[i] = As[ty * 4 + i][kk];
            #pragma unroll
            for (int j = 0; j < 4; j++) b[j] = Bs[tx * 4 + j][kk];
            #pragma unroll
            for (int i = 0; i < 4; i++)
                #pragma unroll
                for (int j = 0; j < 4; j++)
                    acc[i][j] = fmaf(a[i], b[j], acc[i][j]);
        }
        __syncthreads();
    }

    #pragma unroll
    for (int i = 0; i < 4; i++) {
        int m = m0 + ty * 4 + i;
        #pragma unroll
        for (int j = 0; j < 4; j++) {
            int n = n0 + tx * 4 + j;
            C[(size_t)m * N + n] = acc[i][j] + bias[n];
        }
    }
}

// ---------------------------------------------------------------------------
// Flash attention: one block per (q-tile of 64 rows, head, batch).
// Online softmax, key-padding mask (int32, nonzero = masked).
// ---------------------------------------------------------------------------
#define FLASH_SMEM_FLOATS (4 * 64 * 65)
#define FLASH_SMEM_BYTES  (FLASH_SMEM_FLOATS * sizeof(float))

__global__ __launch_bounds__(256) void flash_attn_kernel(
    const float* __restrict__ Qp, const float* __restrict__ Kp,
    const float* __restrict__ Vp, const int* __restrict__ mask,
    float* __restrict__ Out)
{
    extern __shared__ float sm[];
    float (*Qs)[65] = (float(*)[65])(sm);
    float (*Ks)[65] = (float(*)[65])(sm + 1 * 64 * 65);
    float (*Vs)[65] = (float(*)[65])(sm + 2 * 64 * 65);
    float (*Ps)[65] = (float(*)[65])(sm + 3 * 64 * 65);

    const int t  = threadIdx.x;
    const int tx = t & 15;
    const int ty = t >> 4;
    const int qt = blockIdx.x;
    const int h  = blockIdx.y;
    const int b  = blockIdx.z;
    const float scale = 0.125f;  // 1/sqrt(64)
    const size_t headoff = (size_t)h * HD_;

    // Load Q tile [64 x 64]
    #pragma unroll
    for (int s = 0; s < 4; s++) {
        int v = t + s * 256;
        int r = v >> 4;
        int c = (v & 15) << 2;
        float4 q = *reinterpret_cast<const float4*>(
            Qp + (size_t)(b * L_ + qt * 64 + r) * D_ + headoff + c);
        Qs[r][c + 0] = q.x; Qs[r][c + 1] = q.y; Qs[r][c + 2] = q.z; Qs[r][c + 3] = q.w;
    }

    float o[4][4] = {};
    float mrow[4], lrow[4];
    #pragma unroll
    for (int i = 0; i < 4; i++) { mrow[i] = -1e30f; lrow[i] = 0.0f; }

    for (int st = 0; st < 16; st++) {
        __syncthreads();  // protect Ks/Vs/Ps overwrite vs. previous iteration reads

        // Load K and V tiles [64 x 64]
        #pragma unroll
        for (int s = 0; s < 4; s++) {
            int v = t + s * 256;
            int r = v >> 4;
            int c = (v & 15) << 2;
            size_t base = (size_t)(b * L_ + st * 64 + r) * D_ + headoff + c;
            float4 kv = *reinterpret_cast<const float4*>(Kp + base);
            Ks[r][c + 0] = kv.x; Ks[r][c + 1] = kv.y; Ks[r][c + 2] = kv.z; Ks[r][c + 3] = kv.w;
            float4 vv = *reinterpret_cast<const float4*>(Vp + base);
            Vs[r][c + 0] = vv.x; Vs[r][c + 1] = vv.y; Vs[r][c + 2] = vv.z; Vs[r][c + 3] = vv.w;
        }
        __syncthreads();

        // S = Q @ K^T over this tile
        float sacc[4][4] = {};
        #pragma unroll
        for (int kk = 0; kk < 64; kk++) {
            float a[4], bb[4];
            #pragma unroll
            for (int i = 0; i < 4; i++) a[i] = Qs[ty * 4 + i][kk];
            #pragma unroll
            for (int j = 0; j < 4; j++) bb[j] = Ks[tx * 4 + j][kk];
            #pragma unroll
            for (int i = 0; i < 4; i++)
                #pragma unroll
                for (int j = 0; j < 4; j++)
                    sacc[i][j] = fmaf(a[i], bb[j], sacc[i][j]);
        }

        // scale + mask (int32 mask: nonzero = masked)
        bool msk[4];
        #pragma unroll
        for (int j = 0; j < 4; j++)
            msk[j] = mask[(size_t)b * L_ + st * 64 + tx * 4 + j] != 0;
        #pragma unroll
        for (int i = 0; i < 4; i++)
            #pragma unroll
            for (int j = 0; j < 4; j++)
                sacc[i][j] = msk[j] ? -1e30f : sacc[i][j] * scale;

        // online softmax update (rows partitioned by ty; reduce across tx = 16 lanes)
        #pragma unroll
        for (int i = 0; i < 4; i++) {
            float rmax = fmaxf(fmaxf(sacc[i][0], sacc[i][1]), fmaxf(sacc[i][2], sacc[i][3]));
            #pragma unroll
            for (int off = 8; off > 0; off >>= 1)
                rmax = fmaxf(rmax, __shfl_xor_sync(0xffffffffu, rmax, off, 16));
            float mn    = fmaxf(mrow[i], rmax);
            float alpha = __expf(mrow[i] - mn);
            mrow[i] = mn;
            float rs = 0.0f;
            #pragma unroll
            for (int j = 0; j < 4; j++) {
                float p = msk[j] ? 0.0f : __expf(sacc[i][j] - mn);
                sacc[i][j] = p;
                rs += p;
            }
            #pragma unroll
            for (int off = 8; off > 0; off >>= 1)
                rs += __shfl_xor_sync(0xffffffffu, rs, off, 16);
            lrow[i] = lrow[i] * alpha + rs;
            #pragma unroll
            for (int j = 0; j < 4; j++) o[i][j] *= alpha;
        }

        // publish P tile
        #pragma unroll
        for (int i = 0; i < 4; i++)
            #pragma unroll
            for (int j = 0; j < 4; j++)
                Ps[ty * 4 + i][tx * 4 + j] = sacc[i][j];
        __syncthreads();

        // O += P @ V
        #pragma unroll 8
        for (int s = 0; s < 64; s++) {
            float p[4], v[4];
            #pragma unroll
            for (int i = 0; i < 4; i++) p[i] = Ps[ty * 4 + i][s];
            #pragma unroll
            for (int j = 0; j < 4; j++) v[j] = Vs[s][tx * 4 + j];
            #pragma unroll
            for (int i = 0; i < 4; i++)
                #pragma unroll
                for (int j = 0; j < 4; j++)
                    o[i][j] = fmaf(p[i], v[j], o[i][j]);
        }
    }

    // normalize + write
    #pragma unroll
    for (int i = 0; i < 4; i++) {
        float inv = lrow[i] > 0.0f ? 1.0f / lrow[i] : 0.0f;
        int l = qt * 64 + ty * 4 + i;
        #pragma unroll
        for (int j = 0; j < 4; j++)
            Out[(size_t)(b * L_ + l) * D_ + headoff + tx * 4 + j] = o[i][j] * inv;
    }
}

// ---------------------------------------------------------------------------
// Launch
// ---------------------------------------------------------------------------
extern "C" void kernel_launch(void* const* d_in, const int* in_sizes, int n_in,
                              void* d_out, int out_size)
{
    const float* query = (const float*)d_in[0];
    const float* key   = (const float*)d_in[1];
    const float* value = (const float*)d_in[2];
    const int*   mask  = (const int*)d_in[3];   // jax bool -> int32 in harness
    const float* Wq = (const float*)d_in[4];
    const float* bq = (const float*)d_in[5];
    const float* Wk = (const float*)d_in[6];
    const float* bk = (const float*)d_in[7];
    const float* Wv = (const float*)d_in[8];
    const float* bv = (const float*)d_in[9];
    const float* Wo = (const float*)d_in[10];
    const float* bo = (const float*)d_in[11];
    float* out = (float*)d_out;

    void *qp_, *kp_, *vp_, *at_;
    cudaGetSymbolAddress(&qp_, g_Qp);
    cudaGetSymbolAddress(&kp_, g_Kp);
    cudaGetSymbolAddress(&vp_, g_Vp);
    cudaGetSymbolAddress(&at_, g_At);
    float* Qp = (float*)qp_;
    float* Kp = (float*)kp_;
    float* Vp = (float*)vp_;
    float* At = (float*)at_;

    dim3 ggrid(D_ / 64, M_TOT / 64);   // (16, 64)

    gemm_bias_kernel<<<ggrid, 256>>>(query, Wq, bq, Qp, M_TOT, D_, D_);
    gemm_bias_kernel<<<ggrid, 256>>>(key,   Wk, bk, Kp, M_TOT, D_, D_);
    gemm_bias_kernel<<<ggrid, 256>>>(value, Wv, bv, Vp, M_TOT, D_, D_);

    cudaFuncSetAttribute(flash_attn_kernel,
                         cudaFuncAttributeMaxDynamicSharedMemorySize,
                         (int)FLASH_SMEM_BYTES);
    flash_attn_kernel<<<dim3(L_ / 64, H_, B_), 256, FLASH_SMEM_BYTES>>>(
        Qp, Kp, Vp, mask, At);

    gemm_bias_kernel<<<ggrid, 256>>>(At, Wo, bo, out, M_TOT, D_, D_);
}

// round 4
// speedup vs baseline: 1.5281x; 1.5281x over previous
#include <cuda_runtime.h>
#include <cuda_bf16.h>
#include <cstdint>

#define B_   4
#define L_   1024
#define D_   1024
#define H_   16
#define HD_  64
#define M_TOT (B_ * L_)   // 4096

// Scratch (static device globals — allocation-guard safe)
__device__ float g_Qp[M_TOT * D_];
__device__ float g_Kp[M_TOT * D_];
__device__ float g_Vp[M_TOT * D_];
__device__ float g_At[M_TOT * D_];

// ===========================================================================
// Helpers (baseline ISA only: ldmatrix sm_75+, mma.sync bf16 sm_80+)
// ===========================================================================
__device__ __forceinline__ uint32_t smem_u32(const void* p) {
    uint32_t a;
    asm("{ .reg .u64 t; cvta.to.shared.u64 t, %1; cvt.u32.u64 %0, t; }" : "=r"(a) : "l"(p));
    return a;
}
__device__ __forceinline__ void ldsm_x4(uint32_t& r0, uint32_t& r1, uint32_t& r2, uint32_t& r3, uint32_t a) {
    asm volatile("ldmatrix.sync.aligned.m8n8.x4.shared.b16 {%0,%1,%2,%3}, [%4];"
                 : "=r"(r0), "=r"(r1), "=r"(r2), "=r"(r3) : "r"(a));
}
__device__ __forceinline__ void ldsm_x2(uint32_t& r0, uint32_t& r1, uint32_t a) {
    asm volatile("ldmatrix.sync.aligned.m8n8.x2.shared.b16 {%0,%1}, [%2];"
                 : "=r"(r0), "=r"(r1) : "r"(a));
}
__device__ __forceinline__ void mma_bf16(float* c,
    uint32_t a0, uint32_t a1, uint32_t a2, uint32_t a3, uint32_t b0, uint32_t b1) {
    asm volatile("mma.sync.aligned.m16n8k16.row.col.f32.bf16.bf16.f32 "
                 "{%0,%1,%2,%3}, {%4,%5,%6,%7}, {%8,%9}, {%0,%1,%2,%3};"
                 : "+f"(c[0]), "+f"(c[1]), "+f"(c[2]), "+f"(c[3])
                 : "r"(a0), "r"(a1), "r"(a2), "r"(a3), "r"(b0), "r"(b1));
}
__device__ __forceinline__ uint32_t pack_bf16(__nv_bfloat16 lo, __nv_bfloat16 hi) {
    return ((uint32_t)__bfloat16_as_ushort(hi) << 16) | __bfloat16_as_ushort(lo);
}

// ===========================================================================
// HMMA GEMM (bf16x3 split): C[4096,1024] = A[4096,1024] @ W[1024,1024]^T + bias
// Tile 128x128, BK=32, 256 threads, warp tile 64x32, fp32 accum in regs.
// ===========================================================================
#define BKC   32
#define NCH   (D_ / BKC)   // 32
#define SST   40           // smem row stride in bf16 (80B -> conflict-free ldmatrix)

__global__ __launch_bounds__(256, 1) void gemm_hmma_kernel(
    const float* __restrict__ A, const float* __restrict__ W,
    const float* __restrict__ bias, float* __restrict__ C)
{
    __shared__ __align__(16) __nv_bfloat16 Ahi[128][SST];
    __shared__ __align__(16) __nv_bfloat16 Alo[128][SST];
    __shared__ __align__(16) __nv_bfloat16 Bhi[128][SST];
    __shared__ __align__(16) __nv_bfloat16 Blo[128][SST];

    const int t    = threadIdx.x;
    const int lane = t & 31;
    const int warp = t >> 5;
    const int wm   = warp >> 2;   // 0..1
    const int wn   = warp & 3;    // 0..3
    const int m0   = blockIdx.y * 128;
    const int n0   = blockIdx.x * 128;

    float acc[4][4][4];
    #pragma unroll
    for (int i = 0; i < 4; i++)
        #pragma unroll
        for (int j = 0; j < 4; j++)
            #pragma unroll
            for (int r = 0; r < 4; r++) acc[i][j][r] = 0.0f;

    // register prefetch of chunk 0
    float4 pa[4], pb[4];
    #pragma unroll
    for (int i = 0; i < 4; i++) {
        int v = t + i * 256;
        int r = v >> 3;
        int c = (v & 7) << 2;
        pa[i] = *reinterpret_cast<const float4*>(A + (size_t)(m0 + r) * D_ + c);
        pb[i] = *reinterpret_cast<const float4*>(W + (size_t)(n0 + r) * D_ + c);
    }

    for (int ck = 0; ck < NCH; ck++) {
        if (ck) __syncthreads();

        // STS: convert fp32 -> hi/lo bf16
        #pragma unroll
        for (int i = 0; i < 4; i++) {
            int v = t + i * 256;
            int r = v >> 3;
            int c = (v & 7) << 2;

            float4 a = pa[i];
            __nv_bfloat16 h0 = __float2bfloat16(a.x), h1 = __float2bfloat16(a.y);
            __nv_bfloat16 h2 = __float2bfloat16(a.z), h3 = __float2bfloat16(a.w);
            __nv_bfloat16 l0 = __float2bfloat16(a.x - __bfloat162float(h0));
            __nv_bfloat16 l1 = __float2bfloat16(a.y - __bfloat162float(h1));
            __nv_bfloat16 l2 = __float2bfloat16(a.z - __bfloat162float(h2));
            __nv_bfloat16 l3 = __float2bfloat16(a.w - __bfloat162float(h3));
            uint2 hv = { pack_bf16(h0, h1), pack_bf16(h2, h3) };
            uint2 lv = { pack_bf16(l0, l1), pack_bf16(l2, l3) };
            *reinterpret_cast<uint2*>(&Ahi[r][c]) = hv;
            *reinterpret_cast<uint2*>(&Alo[r][c]) = lv;

            float4 w = pb[i];
            h0 = __float2bfloat16(w.x); h1 = __float2bfloat16(w.y);
            h2 = __float2bfloat16(w.z); h3 = __float2bfloat16(w.w);
            l0 = __float2bfloat16(w.x - __bfloat162float(h0));
            l1 = __float2bfloat16(w.y - __bfloat162float(h1));
            l2 = __float2bfloat16(w.z - __bfloat162float(h2));
            l3 = __float2bfloat16(w.w - __bfloat162float(h3));
            hv.x = pack_bf16(h0, h1); hv.y = pack_bf16(h2, h3);
            lv.x = pack_bf16(l0, l1); lv.y = pack_bf16(l2, l3);
            *reinterpret_cast<uint2*>(&Bhi[r][c]) = hv;
            *reinterpret_cast<uint2*>(&Blo[r][c]) = lv;
        }
        __syncthreads();

        // prefetch next chunk (overlaps with MMA below)
        if (ck + 1 < NCH) {
            #pragma unroll
            for (int i = 0; i < 4; i++) {
                int v = t + i * 256;
                int r = v >> 3;
                int c = (v & 7) << 2;
                pa[i] = *reinterpret_cast<const float4*>(A + (size_t)(m0 + r) * D_ + (ck + 1) * BKC + c);
                pb[i] = *reinterpret_cast<const float4*>(W + (size_t)(n0 + r) * D_ + (ck + 1) * BKC + c);
            }
        }

        // compute: 2 k-steps of 16
        #pragma unroll
        for (int ks = 0; ks < 2; ks++) {
            const int k0 = ks * 16;
            uint32_t bh[4][2], bl[4][2];
            #pragma unroll
            for (int j = 0; j < 4; j++) {
                int row = wn * 32 + j * 8 + (lane & 7);
                int col = k0 + (((lane >> 3) & 1) << 3);
                ldsm_x2(bh[j][0], bh[j][1], smem_u32(&Bhi[row][col]));
                ldsm_x2(bl[j][0], bl[j][1], smem_u32(&Blo[row][col]));
            }
            #pragma unroll
            for (int i = 0; i < 4; i++) {
                int row = wm * 64 + i * 16 + (lane & 15);
                int col = k0 + ((lane >> 4) << 3);
                uint32_t ah0, ah1, ah2, ah3, al0, al1, al2, al3;
                ldsm_x4(ah0, ah1, ah2, ah3, smem_u32(&Ahi[row][col]));
                ldsm_x4(al0, al1, al2, al3, smem_u32(&Alo[row][col]));
                #pragma unroll
                for (int j = 0; j < 4; j++) {
                    mma_bf16(acc[i][j], ah0, ah1, ah2, ah3, bh[j][0], bh[j][1]);
                    mma_bf16(acc[i][j], al0, al1, al2, al3, bh[j][0], bh[j][1]);
                    mma_bf16(acc[i][j], ah0, ah1, ah2, ah3, bl[j][0], bl[j][1]);
                }
            }
        }
    }

    // epilogue: direct float2 stores + bias
    const int lr = lane >> 2;
    const int lc = (lane & 3) << 1;
    #pragma unroll
    for (int i = 0; i < 4; i++) {
        #pragma unroll
        for (int j = 0; j < 4; j++) {
            int row = m0 + wm * 64 + i * 16 + lr;
            int col = n0 + wn * 32 + j * 8 + lc;
            float2 bz = *reinterpret_cast<const float2*>(bias + col);
            float2 o0 = { acc[i][j][0] + bz.x, acc[i][j][1] + bz.y };
            float2 o1 = { acc[i][j][2] + bz.x, acc[i][j][3] + bz.y };
            *reinterpret_cast<float2*>(C + (size_t)row * D_ + col) = o0;
            *reinterpret_cast<float2*>(C + (size_t)(row + 8) * D_ + col) = o1;
        }
    }
}

// ---------------------------------------------------------------------------
// Flash attention: unchanged (next optimization target).
// ---------------------------------------------------------------------------
#define FLASH_SMEM_FLOATS (4 * 64 * 65)
#define FLASH_SMEM_BYTES  (FLASH_SMEM_FLOATS * sizeof(float))

__global__ __launch_bounds__(256) void flash_attn_kernel(
    const float* __restrict__ Qp, const float* __restrict__ Kp,
    const float* __restrict__ Vp, const int* __restrict__ mask,
    float* __restrict__ Out)
{
    extern __shared__ float smf[];
    float (*Qs)[65] = (float(*)[65])(smf);
    float (*Ks)[65] = (float(*)[65])(smf + 1 * 64 * 65);
    float (*Vs)[65] = (float(*)[65])(smf + 2 * 64 * 65);
    float (*Ps)[65] = (float(*)[65])(smf + 3 * 64 * 65);

    const int t  = threadIdx.x;
    const int tx = t & 15;
    const int ty = t >> 4;
    const int qt = blockIdx.x;
    const int h  = blockIdx.y;
    const int b  = blockIdx.z;
    const float scale = 0.125f;
    const size_t headoff = (size_t)h * HD_;

    #pragma unroll
    for (int s = 0; s < 4; s++) {
        int v = t + s * 256;
        int r = v >> 4;
        int c = (v & 15) << 2;
        float4 q = *reinterpret_cast<const float4*>(
            Qp + (size_t)(b * L_ + qt * 64 + r) * D_ + headoff + c);
        Qs[r][c + 0] = q.x; Qs[r][c + 1] = q.y; Qs[r][c + 2] = q.z; Qs[r][c + 3] = q.w;
    }

    float o[4][4] = {};
    float mrow[4], lrow[4];
    #pragma unroll
    for (int i = 0; i < 4; i++) { mrow[i] = -1e30f; lrow[i] = 0.0f; }

    for (int st = 0; st < 16; st++) {
        __syncthreads();
        #pragma unroll
        for (int s = 0; s < 4; s++) {
            int v = t + s * 256;
            int r = v >> 4;
            int c = (v & 15) << 2;
            size_t base = (size_t)(b * L_ + st * 64 + r) * D_ + headoff + c;
            float4 kv = *reinterpret_cast<const float4*>(Kp + base);
            Ks[r][c + 0] = kv.x; Ks[r][c + 1] = kv.y; Ks[r][c + 2] = kv.z; Ks[r][c + 3] = kv.w;
            float4 vv = *reinterpret_cast<const float4*>(Vp + base);
            Vs[r][c + 0] = vv.x; Vs[r][c + 1] = vv.y; Vs[r][c + 2] = vv.z; Vs[r][c + 3] = vv.w;
        }
        __syncthreads();

        float sacc[4][4] = {};
        #pragma unroll
        for (int kk = 0; kk < 64; kk++) {
            float a[4], bb[4];
            #pragma unroll
            for (int i = 0; i < 4; i++) a[i] = Qs[ty * 4 + i][kk];
            #pragma unroll
            for (int j = 0; j < 4; j++) bb[j] = Ks[tx * 4 + j][kk];
            #pragma unroll
            for (int i = 0; i < 4; i++)
                #pragma unroll
                for (int j = 0; j < 4; j++)
                    sacc[i][j] = fmaf(a[i], bb[j], sacc[i][j]);
        }

        bool msk[4];
        #pragma unroll
        for (int j = 0; j < 4; j++)
            msk[j] = mask[(size_t)b * L_ + st * 64 + tx * 4 + j] != 0;
        #pragma unroll
        for (int i = 0; i < 4; i++)
            #pragma unroll
            for (int j = 0; j < 4; j++)
                sacc[i][j] = msk[j] ? -1e30f : sacc[i][j] * scale;

        #pragma unroll
        for (int i = 0; i < 4; i++) {
            float rmax = fmaxf(fmaxf(sacc[i][0], sacc[i][1]), fmaxf(sacc[i][2], sacc[i][3]));
            #pragma unroll
            for (int off = 8; off > 0; off >>= 1)
                rmax = fmaxf(rmax, __shfl_xor_sync(0xffffffffu, rmax, off, 16));
            float mn    = fmaxf(mrow[i], rmax);
            float alpha = __expf(mrow[i] - mn);
            mrow[i] = mn;
            float rs = 0.0f;
            #pragma unroll
            for (int j = 0; j < 4; j++) {
                float p = msk[j] ? 0.0f : __expf(sacc[i][j] - mn);
                sacc[i][j] = p;
                rs += p;
            }
            #pragma unroll
            for (int off = 8; off > 0; off >>= 1)
                rs += __shfl_xor_sync(0xffffffffu, rs, off, 16);
            lrow[i] = lrow[i] * alpha + rs;
            #pragma unroll
            for (int j = 0; j < 4; j++) o[i][j] *= alpha;
        }

        #pragma unroll
        for (int i = 0; i < 4; i++)
            #pragma unroll
            for (int j = 0; j < 4; j++)
                Ps[ty * 4 + i][tx * 4 + j] = sacc[i][j];
        __syncthreads();

        #pragma unroll 8
        for (int s = 0; s < 64; s++) {
            float p[4], v[4];
            #pragma unroll
            for (int i = 0; i < 4; i++) p[i] = Ps[ty * 4 + i][s];
            #pragma unroll
            for (int j = 0; j < 4; j++) v[j] = Vs[s][tx * 4 + j];
            #pragma unroll
            for (int i = 0; i < 4; i++)
                #pragma unroll
                for (int j = 0; j < 4; j++)
                    o[i][j] = fmaf(p[i], v[j], o[i][j]);
        }
    }

    #pragma unroll
    for (int i = 0; i < 4; i++) {
        float inv = lrow[i] > 0.0f ? 1.0f / lrow[i] : 0.0f;
        int l = qt * 64 + ty * 4 + i;
        #pragma unroll
        for (int j = 0; j < 4; j++)
            Out[(size_t)(b * L_ + l) * D_ + headoff + tx * 4 + j] = o[i][j] * inv;
    }
}

// ---------------------------------------------------------------------------
// Launch
// ---------------------------------------------------------------------------
extern "C" void kernel_launch(void* const* d_in, const int* in_sizes, int n_in,
                              void* d_out, int out_size)
{
    const float* query = (const float*)d_in[0];
    const float* key   = (const float*)d_in[1];
    const float* value = (const float*)d_in[2];
    const int*   mask  = (const int*)d_in[3];
    const float* Wq = (const float*)d_in[4];
    const float* bq = (const float*)d_in[5];
    const float* Wk = (const float*)d_in[6];
    const float* bk = (const float*)d_in[7];
    const float* Wv = (const float*)d_in[8];
    const float* bv = (const float*)d_in[9];
    const float* Wo = (const float*)d_in[10];
    const float* bo = (const float*)d_in[11];
    float* out = (float*)d_out;

    void *qp_, *kp_, *vp_, *at_;
    cudaGetSymbolAddress(&qp_, g_Qp);
    cudaGetSymbolAddress(&kp_, g_Kp);
    cudaGetSymbolAddress(&vp_, g_Vp);
    cudaGetSymbolAddress(&at_, g_At);
    float* Qp = (float*)qp_;
    float* Kp = (float*)kp_;
    float* Vp = (float*)vp_;
    float* At = (float*)at_;

    cudaFuncSetAttribute(flash_attn_kernel,
                         cudaFuncAttributeMaxDynamicSharedMemorySize,
                         (int)FLASH_SMEM_BYTES);

    dim3 tgrid(D_ / 128, M_TOT / 128);   // (8, 32)

    gemm_hmma_kernel<<<tgrid, 256>>>(query, Wq, bq, Qp);
    gemm_hmma_kernel<<<tgrid, 256>>>(key,   Wk, bk, Kp);
    gemm_hmma_kernel<<<tgrid, 256>>>(value, Wv, bv, Vp);

    flash_attn_kernel<<<dim3(L_ / 64, H_, B_), 256, FLASH_SMEM_BYTES>>>(
        Qp, Kp, Vp, mask, At);

    gemm_hmma_kernel<<<tgrid, 256>>>(At, Wo, bo, out);
}

// round 6
// speedup vs baseline: 2.3196x; 1.5179x over previous
#include <cuda_runtime.h>
#include <cuda_bf16.h>
#include <cstdint>

#define B_   4
#define L_   1024
#define D_   1024
#define H_   16
#define HD_  64
#define M_TOT (B_ * L_)   // 4096

// Scratch (static device globals — allocation-guard safe)
__device__ __nv_bfloat16 g_Qhi[M_TOT * D_];
__device__ __nv_bfloat16 g_Qlo[M_TOT * D_];
__device__ __nv_bfloat16 g_Khi[M_TOT * D_];
__device__ __nv_bfloat16 g_Klo[M_TOT * D_];
__device__ __nv_bfloat16 g_Vhi[M_TOT * D_];
__device__ __nv_bfloat16 g_Vlo[M_TOT * D_];
__device__ float g_At[M_TOT * D_];

// ===========================================================================
// Helpers (baseline ISA: ldmatrix sm_75+, mma.sync bf16 sm_80+)
// ===========================================================================
__device__ __forceinline__ uint32_t smem_u32(const void* p) {
    uint32_t a;
    asm("{ .reg .u64 t; cvta.to.shared.u64 t, %1; cvt.u32.u64 %0, t; }" : "=r"(a) : "l"(p));
    return a;
}
__device__ __forceinline__ void ldsm_x4(uint32_t& r0, uint32_t& r1, uint32_t& r2, uint32_t& r3, uint32_t a) {
    asm volatile("ldmatrix.sync.aligned.m8n8.x4.shared.b16 {%0,%1,%2,%3}, [%4];"
                 : "=r"(r0), "=r"(r1), "=r"(r2), "=r"(r3) : "r"(a));
}
__device__ __forceinline__ void ldsm_x2(uint32_t& r0, uint32_t& r1, uint32_t a) {
    asm volatile("ldmatrix.sync.aligned.m8n8.x2.shared.b16 {%0,%1}, [%2];"
                 : "=r"(r0), "=r"(r1) : "r"(a));
}
__device__ __forceinline__ void ldsm_x2t(uint32_t& r0, uint32_t& r1, uint32_t a) {
    asm volatile("ldmatrix.sync.aligned.m8n8.x2.trans.shared.b16 {%0,%1}, [%2];"
                 : "=r"(r0), "=r"(r1) : "r"(a));
}
__device__ __forceinline__ void mma_bf16(float* c,
    uint32_t a0, uint32_t a1, uint32_t a2, uint32_t a3, uint32_t b0, uint32_t b1) {
    asm volatile("mma.sync.aligned.m16n8k16.row.col.f32.bf16.bf16.f32 "
                 "{%0,%1,%2,%3}, {%4,%5,%6,%7}, {%8,%9}, {%0,%1,%2,%3};"
                 : "+f"(c[0]), "+f"(c[1]), "+f"(c[2]), "+f"(c[3])
                 : "r"(a0), "r"(a1), "r"(a2), "r"(a3), "r"(b0), "r"(b1));
}
__device__ __forceinline__ uint32_t pack_bf16(__nv_bfloat16 lo, __nv_bfloat16 hi) {
    return ((uint32_t)__bfloat16_as_ushort(hi) << 16) | __bfloat16_as_ushort(lo);
}
__device__ __forceinline__ void split2(float x, __nv_bfloat16& h, __nv_bfloat16& l) {
    h = __float2bfloat16(x);
    l = __float2bfloat16(x - __bfloat162float(h));
}

// ===========================================================================
// HMMA GEMM (bf16x3 split): C = A[4096,1024] @ W[1024,1024]^T + bias.
// Output: fp32 C (if Clo==nullptr) or split hi/lo bf16 (Chi/Clo).
// ===========================================================================
#define BKC   32
#define NCH   (D_ / BKC)   // 32
#define SST   40

__global__ __launch_bounds__(256, 1) void gemm_hmma_kernel(
    const float* __restrict__ A, const float* __restrict__ W,
    const float* __restrict__ bias, float* __restrict__ C,
    __nv_bfloat16* __restrict__ Chi, __nv_bfloat16* __restrict__ Clo)
{
    __shared__ __align__(16) __nv_bfloat16 Ahi[128][SST];
    __shared__ __align__(16) __nv_bfloat16 Alo[128][SST];
    __shared__ __align__(16) __nv_bfloat16 Bhi[128][SST];
    __shared__ __align__(16) __nv_bfloat16 Blo[128][SST];

    const int t    = threadIdx.x;
    const int lane = t & 31;
    const int warp = t >> 5;
    const int wm   = warp >> 2;
    const int wn   = warp & 3;
    const int m0   = blockIdx.y * 128;
    const int n0   = blockIdx.x * 128;

    float acc[4][4][4];
    #pragma unroll
    for (int i = 0; i < 4; i++)
        #pragma unroll
        for (int j = 0; j < 4; j++)
            #pragma unroll
            for (int r = 0; r < 4; r++) acc[i][j][r] = 0.0f;

    float4 pa[4], pb[4];
    #pragma unroll
    for (int i = 0; i < 4; i++) {
        int v = t + i * 256;
        int r = v >> 3;
        int c = (v & 7) << 2;
        pa[i] = *reinterpret_cast<const float4*>(A + (size_t)(m0 + r) * D_ + c);
        pb[i] = *reinterpret_cast<const float4*>(W + (size_t)(n0 + r) * D_ + c);
    }

    for (int ck = 0; ck < NCH; ck++) {
        if (ck) __syncthreads();

        #pragma unroll
        for (int i = 0; i < 4; i++) {
            int v = t + i * 256;
            int r = v >> 3;
            int c = (v & 7) << 2;

            float4 a = pa[i];
            __nv_bfloat16 h0, h1, h2, h3, l0, l1, l2, l3;
            split2(a.x, h0, l0); split2(a.y, h1, l1);
            split2(a.z, h2, l2); split2(a.w, h3, l3);
            uint2 hv = { pack_bf16(h0, h1), pack_bf16(h2, h3) };
            uint2 lv = { pack_bf16(l0, l1), pack_bf16(l2, l3) };
            *reinterpret_cast<uint2*>(&Ahi[r][c]) = hv;
            *reinterpret_cast<uint2*>(&Alo[r][c]) = lv;

            float4 w = pb[i];
            split2(w.x, h0, l0); split2(w.y, h1, l1);
            split2(w.z, h2, l2); split2(w.w, h3, l3);
            hv.x = pack_bf16(h0, h1); hv.y = pack_bf16(h2, h3);
            lv.x = pack_bf16(l0, l1); lv.y = pack_bf16(l2, l3);
            *reinterpret_cast<uint2*>(&Bhi[r][c]) = hv;
            *reinterpret_cast<uint2*>(&Blo[r][c]) = lv;
        }
        __syncthreads();

        if (ck + 1 < NCH) {
            #pragma unroll
            for (int i = 0; i < 4; i++) {
                int v = t + i * 256;
                int r = v >> 3;
                int c = (v & 7) << 2;
                pa[i] = *reinterpret_cast<const float4*>(A + (size_t)(m0 + r) * D_ + (ck + 1) * BKC + c);
                pb[i] = *reinterpret_cast<const float4*>(W + (size_t)(n0 + r) * D_ + (ck + 1) * BKC + c);
            }
        }

        #pragma unroll
        for (int ks = 0; ks < 2; ks++) {
            const int k0 = ks * 16;
            uint32_t bh[4][2], bl[4][2];
            #pragma unroll
            for (int j = 0; j < 4; j++) {
                int row = wn * 32 + j * 8 + (lane & 7);
                int col = k0 + (((lane >> 3) & 1) << 3);
                ldsm_x2(bh[j][0], bh[j][1], smem_u32(&Bhi[row][col]));
                ldsm_x2(bl[j][0], bl[j][1], smem_u32(&Blo[row][col]));
            }
            #pragma unroll
            for (int i = 0; i < 4; i++) {
                int row = wm * 64 + i * 16 + (lane & 15);
                int col = k0 + ((lane >> 4) << 3);
                uint32_t ah0, ah1, ah2, ah3, al0, al1, al2, al3;
                ldsm_x4(ah0, ah1, ah2, ah3, smem_u32(&Ahi[row][col]));
                ldsm_x4(al0, al1, al2, al3, smem_u32(&Alo[row][col]));
                #pragma unroll
                for (int j = 0; j < 4; j++) {
                    mma_bf16(acc[i][j], ah0, ah1, ah2, ah3, bh[j][0], bh[j][1]);
                    mma_bf16(acc[i][j], al0, al1, al2, al3, bh[j][0], bh[j][1]);
                    mma_bf16(acc[i][j], ah0, ah1, ah2, ah3, bl[j][0], bl[j][1]);
                }
            }
        }
    }

    const int lr = lane >> 2;
    const int lc = (lane & 3) << 1;
    #pragma unroll
    for (int i = 0; i < 4; i++) {
        #pragma unroll
        for (int j = 0; j < 4; j++) {
            int row = m0 + wm * 64 + i * 16 + lr;
            int col = n0 + wn * 32 + j * 8 + lc;
            float2 bz = *reinterpret_cast<const float2*>(bias + col);
            float v0 = acc[i][j][0] + bz.x, v1 = acc[i][j][1] + bz.y;
            float v2 = acc[i][j][2] + bz.x, v3 = acc[i][j][3] + bz.y;
            if (Clo) {
                __nv_bfloat16 h0, h1, h2, h3, l0, l1, l2, l3;
                split2(v0, h0, l0); split2(v1, h1, l1);
                split2(v2, h2, l2); split2(v3, h3, l3);
                *reinterpret_cast<uint32_t*>(Chi + (size_t)row * D_ + col)       = pack_bf16(h0, h1);
                *reinterpret_cast<uint32_t*>(Clo + (size_t)row * D_ + col)       = pack_bf16(l0, l1);
                *reinterpret_cast<uint32_t*>(Chi + (size_t)(row + 8) * D_ + col) = pack_bf16(h2, h3);
                *reinterpret_cast<uint32_t*>(Clo + (size_t)(row + 8) * D_ + col) = pack_bf16(l2, l3);
            } else {
                float2 o0 = { v0, v1 }, o1 = { v2, v3 };
                *reinterpret_cast<float2*>(C + (size_t)row * D_ + col) = o0;
                *reinterpret_cast<float2*>(C + (size_t)(row + 8) * D_ + col) = o1;
            }
        }
    }
}

// ===========================================================================
// HMMA flash attention (bf16x3 split QK^T and PV, fp32 softmax/accum).
// CTA = (64 q rows, head, batch); 4 warps x m16; BN=64 keys/iter; HD=64.
// ===========================================================================
#define FST 72   // smem row stride in bf16 (144B): conflict-free ldmatrix

__global__ __launch_bounds__(128) void flash_hmma_kernel(
    const __nv_bfloat16* __restrict__ Qhi, const __nv_bfloat16* __restrict__ Qlo,
    const __nv_bfloat16* __restrict__ Khi, const __nv_bfloat16* __restrict__ Klo,
    const __nv_bfloat16* __restrict__ Vhi, const __nv_bfloat16* __restrict__ Vlo,
    const int* __restrict__ mask, float* __restrict__ Out)
{
    __shared__ __align__(16) __nv_bfloat16 KH[64][FST];
    __shared__ __align__(16) __nv_bfloat16 KL[64][FST];
    __shared__ __align__(16) __nv_bfloat16 VH[64][FST];
    __shared__ __align__(16) __nv_bfloat16 VL[64][FST];
    __shared__ float MF[64];

    const int t    = threadIdx.x;
    const int lane = t & 31;
    const int warp = t >> 5;
    const int qt   = blockIdx.x;
    const int h    = blockIdx.y;
    const int b    = blockIdx.z;
    const int grow0 = b * L_ + qt * 64;
    const int ghc   = h * HD_;
    const float scale = 0.125f;

    // ---- stage Q tile through KH/KL, read fragments into registers ----
    #pragma unroll
    for (int i = 0; i < 4; i++) {
        int v = t + i * 128;
        int r = v >> 3;
        int c = (v & 7) << 3;
        *reinterpret_cast<uint4*>(&KH[r][c]) =
            *reinterpret_cast<const uint4*>(Qhi + (size_t)(grow0 + r) * D_ + ghc + c);
        *reinterpret_cast<uint4*>(&KL[r][c]) =
            *reinterpret_cast<const uint4*>(Qlo + (size_t)(grow0 + r) * D_ + ghc + c);
    }
    __syncthreads();

    uint32_t qh[4][4], ql[4][4];
    {
        int ar = warp * 16 + (lane & 15);
        int ac = (lane >> 4) << 3;
        #pragma unroll
        for (int kc = 0; kc < 4; kc++) {
            ldsm_x4(qh[kc][0], qh[kc][1], qh[kc][2], qh[kc][3], smem_u32(&KH[ar][kc * 16 + ac]));
            ldsm_x4(ql[kc][0], ql[kc][1], ql[kc][2], ql[kc][3], smem_u32(&KL[ar][kc * 16 + ac]));
        }
    }

    float O[8][4];
    #pragma unroll
    for (int j = 0; j < 8; j++)
        #pragma unroll
        for (int r = 0; r < 4; r++) O[j][r] = 0.0f;
    float m0 = -1e30f, m1 = -1e30f, l0 = 0.0f, l1 = 0.0f;

    for (int kt = 0; kt < 16; kt++) {
        __syncthreads();   // previous-iteration reads done (also covers Q staging)
        const int krow0 = b * L_ + kt * 64;
        #pragma unroll
        for (int i = 0; i < 4; i++) {
            int v = t + i * 128;
            int r = v >> 3;
            int c = (v & 7) << 3;
            size_t gb = (size_t)(krow0 + r) * D_ + ghc + c;
            *reinterpret_cast<uint4*>(&KH[r][c]) = *reinterpret_cast<const uint4*>(Khi + gb);
            *reinterpret_cast<uint4*>(&KL[r][c]) = *reinterpret_cast<const uint4*>(Klo + gb);
            *reinterpret_cast<uint4*>(&VH[r][c]) = *reinterpret_cast<const uint4*>(Vhi + gb);
            *reinterpret_cast<uint4*>(&VL[r][c]) = *reinterpret_cast<const uint4*>(Vlo + gb);
        }
        if (t < 64) MF[t] = mask[b * L_ + kt * 64 + t] ? -1e30f : 0.0f;
        __syncthreads();

        // ---- S = Q K^T (split) ----
        float S[8][4];
        #pragma unroll
        for (int j = 0; j < 8; j++) {
            S[j][0] = S[j][1] = S[j][2] = S[j][3] = 0.0f;
            int brow = j * 8 + (lane & 7);
            #pragma unroll
            for (int kc = 0; kc < 4; kc++) {
                int bcol = kc * 16 + (((lane >> 3) & 1) << 3);
                uint32_t bh0, bh1, bl0, bl1;
                ldsm_x2(bh0, bh1, smem_u32(&KH[brow][bcol]));
                ldsm_x2(bl0, bl1, smem_u32(&KL[brow][bcol]));
                mma_bf16(S[j], qh[kc][0], qh[kc][1], qh[kc][2], qh[kc][3], bh0, bh1);
                mma_bf16(S[j], ql[kc][0], ql[kc][1], ql[kc][2], ql[kc][3], bh0, bh1);
                mma_bf16(S[j], qh[kc][0], qh[kc][1], qh[kc][2], qh[kc][3], bl0, bl1);
            }
        }

        // ---- softmax (fragment layout: rows l/4, l/4+8; cols 8j+2(l%4)+{0,1}) ----
        float rmax0 = -3.0e38f, rmax1 = -3.0e38f;
        #pragma unroll
        for (int j = 0; j < 8; j++) {
            float ma = MF[j * 8 + ((lane & 3) << 1)];
            float mb = MF[j * 8 + ((lane & 3) << 1) + 1];
            S[j][0] = S[j][0] * scale + ma;
            S[j][1] = S[j][1] * scale + mb;
            S[j][2] = S[j][2] * scale + ma;
            S[j][3] = S[j][3] * scale + mb;
            rmax0 = fmaxf(rmax0, fmaxf(S[j][0], S[j][1]));
            rmax1 = fmaxf(rmax1, fmaxf(S[j][2], S[j][3]));
        }
        rmax0 = fmaxf(rmax0, __shfl_xor_sync(0xffffffffu, rmax0, 1));
        rmax0 = fmaxf(rmax0, __shfl_xor_sync(0xffffffffu, rmax0, 2));
        rmax1 = fmaxf(rmax1, __shfl_xor_sync(0xffffffffu, rmax1, 1));
        rmax1 = fmaxf(rmax1, __shfl_xor_sync(0xffffffffu, rmax1, 2));

        float mn0 = fmaxf(m0, rmax0), mn1 = fmaxf(m1, rmax1);
        float a0 = __expf(m0 - mn0), a1 = __expf(m1 - mn1);
        m0 = mn0; m1 = mn1;

        float sum0 = 0.0f, sum1 = 0.0f;
        #pragma unroll
        for (int j = 0; j < 8; j++) {
            S[j][0] = __expf(S[j][0] - mn0); sum0 += S[j][0];
            S[j][1] = __expf(S[j][1] - mn0); sum0 += S[j][1];
            S[j][2] = __expf(S[j][2] - mn1); sum1 += S[j][2];
            S[j][3] = __expf(S[j][3] - mn1); sum1 += S[j][3];
        }
        sum0 += __shfl_xor_sync(0xffffffffu, sum0, 1);
        sum0 += __shfl_xor_sync(0xffffffffu, sum0, 2);
        sum1 += __shfl_xor_sync(0xffffffffu, sum1, 1);
        sum1 += __shfl_xor_sync(0xffffffffu, sum1, 2);
        l0 = l0 * a0 + sum0;
        l1 = l1 * a1 + sum1;

        #pragma unroll
        for (int j = 0; j < 8; j++) {
            O[j][0] *= a0; O[j][1] *= a0; O[j][2] *= a1; O[j][3] *= a1;
        }

        // ---- split P into hi/lo A-fragments (C-frag layout == A-frag layout) ----
        uint32_t ph[4][4], pl[4][4];
        #pragma unroll
        for (int kc = 0; kc < 4; kc++) {
            const float* x = S[2 * kc];
            const float* y = S[2 * kc + 1];
            __nv_bfloat16 h0, h1, h2, h3, g0, g1, g2, g3;
            __nv_bfloat16 e0, e1, e2, e3, f0, f1, f2, f3;
            split2(x[0], h0, e0); split2(x[1], h1, e1);
            split2(x[2], h2, e2); split2(x[3], h3, e3);
            split2(y[0], g0, f0); split2(y[1], g1, f1);
            split2(y[2], g2, f2); split2(y[3], g3, f3);
            ph[kc][0] = pack_bf16(h0, h1); ph[kc][1] = pack_bf16(h2, h3);
            ph[kc][2] = pack_bf16(g0, g1); ph[kc][3] = pack_bf16(g2, g3);
            pl[kc][0] = pack_bf16(e0, e1); pl[kc][1] = pack_bf16(e2, e3);
            pl[kc][2] = pack_bf16(f0, f1); pl[kc][3] = pack_bf16(f2, f3);
        }

        // ---- O += P V (split); V via ldmatrix.trans ----
        #pragma unroll
        for (int jn = 0; jn < 8; jn++) {
            #pragma unroll
            for (int kc = 0; kc < 4; kc++) {
                int vrow = kc * 16 + (lane & 15);
                uint32_t vh0, vh1, vl0, vl1;
                ldsm_x2t(vh0, vh1, smem_u32(&VH[vrow][jn * 8]));
                ldsm_x2t(vl0, vl1, smem_u32(&VL[vrow][jn * 8]));
                mma_bf16(O[jn], ph[kc][0], ph[kc][1], ph[kc][2], ph[kc][3], vh0, vh1);
                mma_bf16(O[jn], pl[kc][0], pl[kc][1], pl[kc][2], pl[kc][3], vh0, vh1);
                mma_bf16(O[jn], ph[kc][0], ph[kc][1], ph[kc][2], ph[kc][3], vl0, vl1);
            }
        }
    }

    // ---- normalize + write ----
    float inv0 = l0 > 0.0f ? 1.0f / l0 : 0.0f;
    float inv1 = l1 > 0.0f ? 1.0f / l1 : 0.0f;
    int row0 = grow0 + warp * 16 + (lane >> 2);
    int col  = ghc + ((lane & 3) << 1);
    #pragma unroll
    for (int jn = 0; jn < 8; jn++) {
        float2 o0 = { O[jn][0] * inv0, O[jn][1] * inv0 };
        float2 o1 = { O[jn][2] * inv1, O[jn][3] * inv1 };
        *reinterpret_cast<float2*>(Out + (size_t)row0 * D_ + col + jn * 8) = o0;
        *reinterpret_cast<float2*>(Out + (size_t)(row0 + 8) * D_ + col + jn * 8) = o1;
    }
}

// ---------------------------------------------------------------------------
// Launch
// ---------------------------------------------------------------------------
extern "C" void kernel_launch(void* const* d_in, const int* in_sizes, int n_in,
                              void* d_out, int out_size)
{
    const float* query = (const float*)d_in[0];
    const float* key   = (const float*)d_in[1];
    const float* value = (const float*)d_in[2];
    const int*   mask  = (const int*)d_in[3];
    const float* Wq = (const float*)d_in[4];
    const float* bq = (const float*)d_in[5];
    const float* Wk = (const float*)d_in[6];
    const float* bk = (const float*)d_in[7];
    const float* Wv = (const float*)d_in[8];
    const float* bv = (const float*)d_in[9];
    const float* Wo = (const float*)d_in[10];
    const float* bo = (const float*)d_in[11];
    float* out = (float*)d_out;

    void *qh_, *ql_, *kh_, *kl_, *vh_, *vl_, *at_;
    cudaGetSymbolAddress(&qh_, g_Qhi); cudaGetSymbolAddress(&ql_, g_Qlo);
    cudaGetSymbolAddress(&kh_, g_Khi); cudaGetSymbolAddress(&kl_, g_Klo);
    cudaGetSymbolAddress(&vh_, g_Vhi); cudaGetSymbolAddress(&vl_, g_Vlo);
    cudaGetSymbolAddress(&at_, g_At);
    __nv_bfloat16* Qhi = (__nv_bfloat16*)qh_; __nv_bfloat16* Qlo = (__nv_bfloat16*)ql_;
    __nv_bfloat16* Khi = (__nv_bfloat16*)kh_; __nv_bfloat16* Klo = (__nv_bfloat16*)kl_;
    __nv_bfloat16* Vhi = (__nv_bfloat16*)vh_; __nv_bfloat16* Vlo = (__nv_bfloat16*)vl_;
    float* At = (float*)at_;

    dim3 tgrid(D_ / 128, M_TOT / 128);   // (8, 32)

    gemm_hmma_kernel<<<tgrid, 256>>>(query, Wq, bq, nullptr, Qhi, Qlo);
    gemm_hmma_kernel<<<tgrid, 256>>>(key,   Wk, bk, nullptr, Khi, Klo);
    gemm_hmma_kernel<<<tgrid, 256>>>(value, Wv, bv, nullptr, Vhi, Vlo);

    flash_hmma_kernel<<<dim3(L_ / 64, H_, B_), 128>>>(
        Qhi, Qlo, Khi, Klo, Vhi, Vlo, mask, At);

    gemm_hmma_kernel<<<tgrid, 256>>>(At, Wo, bo, out, nullptr, nullptr);
}

// round 7
// speedup vs baseline: 3.0272x; 1.3051x over previous
#include <cuda_runtime.h>
#include <cuda_fp16.h>
#include <cstdint>

#define B_   4
#define L_   1024
#define D_   1024
#define H_   16
#define HD_  64
#define M_TOT (B_ * L_)   // 4096

// Scratch (static device globals — allocation-guard safe)
__device__ __half g_Qhi[M_TOT * D_];
__device__ __half g_Qlo[M_TOT * D_];
__device__ __half g_Khi[M_TOT * D_];
__device__ __half g_Vhi[M_TOT * D_];
__device__ float  g_At[M_TOT * D_];

// ===========================================================================
// Helpers (baseline ISA: ldmatrix sm_75+, mma.sync fp16 sm_80+)
// ===========================================================================
__device__ __forceinline__ uint32_t smem_u32(const void* p) {
    uint32_t a;
    asm("{ .reg .u64 t; cvta.to.shared.u64 t, %1; cvt.u32.u64 %0, t; }" : "=r"(a) : "l"(p));
    return a;
}
__device__ __forceinline__ void ldsm_x4(uint32_t& r0, uint32_t& r1, uint32_t& r2, uint32_t& r3, uint32_t a) {
    asm volatile("ldmatrix.sync.aligned.m8n8.x4.shared.b16 {%0,%1,%2,%3}, [%4];"
                 : "=r"(r0), "=r"(r1), "=r"(r2), "=r"(r3) : "r"(a));
}
__device__ __forceinline__ void ldsm_x2(uint32_t& r0, uint32_t& r1, uint32_t a) {
    asm volatile("ldmatrix.sync.aligned.m8n8.x2.shared.b16 {%0,%1}, [%2];"
                 : "=r"(r0), "=r"(r1) : "r"(a));
}
__device__ __forceinline__ void ldsm_x2t(uint32_t& r0, uint32_t& r1, uint32_t a) {
    asm volatile("ldmatrix.sync.aligned.m8n8.x2.trans.shared.b16 {%0,%1}, [%2];"
                 : "=r"(r0), "=r"(r1) : "r"(a));
}
__device__ __forceinline__ void mma_f16(float* c,
    uint32_t a0, uint32_t a1, uint32_t a2, uint32_t a3, uint32_t b0, uint32_t b1) {
    asm volatile("mma.sync.aligned.m16n8k16.row.col.f32.f16.f16.f32 "
                 "{%0,%1,%2,%3}, {%4,%5,%6,%7}, {%8,%9}, {%0,%1,%2,%3};"
                 : "+f"(c[0]), "+f"(c[1]), "+f"(c[2]), "+f"(c[3])
                 : "r"(a0), "r"(a1), "r"(a2), "r"(a3), "r"(b0), "r"(b1));
}
__device__ __forceinline__ uint32_t pack_h(__half lo, __half hi) {
    return ((uint32_t)__half_as_ushort(hi) << 16) | __half_as_ushort(lo);
}
__device__ __forceinline__ void split2h(float x, __half& h, __half& l) {
    h = __float2half_rn(x);
    l = __float2half_rn(x - __half2float(h));
}

// ===========================================================================
// HMMA GEMM (fp16 2-term split): C = A[4096,1024] @ W[1024,1024]^T + bias.
//   A split into hi/lo fp16; W rounded to single fp16 (hi).
//   C += Ahi*Whi + Alo*Whi   (dropped Ahi*Wlo ~ 1.4e-4 relative)
// Output modes: fp32 C | split (Chi,Clo) | hi-only (Chi, Clo=null)
// ===========================================================================
#define BKC   32
#define NCH   (D_ / BKC)   // 32
#define SST   40

__global__ __launch_bounds__(256, 1) void gemm_hmma_kernel(
    const float* __restrict__ A, const float* __restrict__ W,
    const float* __restrict__ bias, float* __restrict__ C,
    __half* __restrict__ Chi, __half* __restrict__ Clo)
{
    __shared__ __align__(16) __half Ahi[128][SST];
    __shared__ __align__(16) __half Alo[128][SST];
    __shared__ __align__(16) __half Bhi[128][SST];

    const int t    = threadIdx.x;
    const int lane = t & 31;
    const int warp = t >> 5;
    const int wm   = warp >> 2;
    const int wn   = warp & 3;
    const int m0   = blockIdx.y * 128;
    const int n0   = blockIdx.x * 128;

    float acc[4][4][4];
    #pragma unroll
    for (int i = 0; i < 4; i++)
        #pragma unroll
        for (int j = 0; j < 4; j++)
            #pragma unroll
            for (int r = 0; r < 4; r++) acc[i][j][r] = 0.0f;

    float4 pa[4], pb[4];
    #pragma unroll
    for (int i = 0; i < 4; i++) {
        int v = t + i * 256;
        int r = v >> 3;
        int c = (v & 7) << 2;
        pa[i] = *reinterpret_cast<const float4*>(A + (size_t)(m0 + r) * D_ + c);
        pb[i] = *reinterpret_cast<const float4*>(W + (size_t)(n0 + r) * D_ + c);
    }

    for (int ck = 0; ck < NCH; ck++) {
        if (ck) __syncthreads();

        #pragma unroll
        for (int i = 0; i < 4; i++) {
            int v = t + i * 256;
            int r = v >> 3;
            int c = (v & 7) << 2;

            float4 a = pa[i];
            __half h0, h1, h2, h3, l0, l1, l2, l3;
            split2h(a.x, h0, l0); split2h(a.y, h1, l1);
            split2h(a.z, h2, l2); split2h(a.w, h3, l3);
            uint2 hv = { pack_h(h0, h1), pack_h(h2, h3) };
            uint2 lv = { pack_h(l0, l1), pack_h(l2, l3) };
            *reinterpret_cast<uint2*>(&Ahi[r][c]) = hv;
            *reinterpret_cast<uint2*>(&Alo[r][c]) = lv;

            float4 w = pb[i];
            uint2 wv = { pack_h(__float2half_rn(w.x), __float2half_rn(w.y)),
                         pack_h(__float2half_rn(w.z), __float2half_rn(w.w)) };
            *reinterpret_cast<uint2*>(&Bhi[r][c]) = wv;
        }
        __syncthreads();

        if (ck + 1 < NCH) {
            #pragma unroll
            for (int i = 0; i < 4; i++) {
                int v = t + i * 256;
                int r = v >> 3;
                int c = (v & 7) << 2;
                pa[i] = *reinterpret_cast<const float4*>(A + (size_t)(m0 + r) * D_ + (ck + 1) * BKC + c);
                pb[i] = *reinterpret_cast<const float4*>(W + (size_t)(n0 + r) * D_ + (ck + 1) * BKC + c);
            }
        }

        #pragma unroll
        for (int ks = 0; ks < 2; ks++) {
            const int k0 = ks * 16;
            uint32_t bh[4][2];
            #pragma unroll
            for (int j = 0; j < 4; j++) {
                int row = wn * 32 + j * 8 + (lane & 7);
                int col = k0 + (((lane >> 3) & 1) << 3);
                ldsm_x2(bh[j][0], bh[j][1], smem_u32(&Bhi[row][col]));
            }
            #pragma unroll
            for (int i = 0; i < 4; i++) {
                int row = wm * 64 + i * 16 + (lane & 15);
                int col = k0 + ((lane >> 4) << 3);
                uint32_t ah0, ah1, ah2, ah3, al0, al1, al2, al3;
                ldsm_x4(ah0, ah1, ah2, ah3, smem_u32(&Ahi[row][col]));
                ldsm_x4(al0, al1, al2, al3, smem_u32(&Alo[row][col]));
                #pragma unroll
                for (int j = 0; j < 4; j++) {
                    mma_f16(acc[i][j], ah0, ah1, ah2, ah3, bh[j][0], bh[j][1]);
                    mma_f16(acc[i][j], al0, al1, al2, al3, bh[j][0], bh[j][1]);
                }
            }
        }
    }

    const int lr = lane >> 2;
    const int lc = (lane & 3) << 1;
    #pragma unroll
    for (int i = 0; i < 4; i++) {
        #pragma unroll
        for (int j = 0; j < 4; j++) {
            int row = m0 + wm * 64 + i * 16 + lr;
            int col = n0 + wn * 32 + j * 8 + lc;
            float2 bz = *reinterpret_cast<const float2*>(bias + col);
            float v0 = acc[i][j][0] + bz.x, v1 = acc[i][j][1] + bz.y;
            float v2 = acc[i][j][2] + bz.x, v3 = acc[i][j][3] + bz.y;
            if (Chi) {
                if (Clo) {
                    __half h0, h1, h2, h3, l0, l1, l2, l3;
                    split2h(v0, h0, l0); split2h(v1, h1, l1);
                    split2h(v2, h2, l2); split2h(v3, h3, l3);
                    *reinterpret_cast<uint32_t*>(Chi + (size_t)row * D_ + col)       = pack_h(h0, h1);
                    *reinterpret_cast<uint32_t*>(Clo + (size_t)row * D_ + col)       = pack_h(l0, l1);
                    *reinterpret_cast<uint32_t*>(Chi + (size_t)(row + 8) * D_ + col) = pack_h(h2, h3);
                    *reinterpret_cast<uint32_t*>(Clo + (size_t)(row + 8) * D_ + col) = pack_h(l2, l3);
                } else {
                    *reinterpret_cast<uint32_t*>(Chi + (size_t)row * D_ + col) =
                        pack_h(__float2half_rn(v0), __float2half_rn(v1));
                    *reinterpret_cast<uint32_t*>(Chi + (size_t)(row + 8) * D_ + col) =
                        pack_h(__float2half_rn(v2), __float2half_rn(v3));
                }
            } else {
                float2 o0 = { v0, v1 }, o1 = { v2, v3 };
                *reinterpret_cast<float2*>(C + (size_t)row * D_ + col) = o0;
                *reinterpret_cast<float2*>(C + (size_t)(row + 8) * D_ + col) = o1;
            }
        }
    }
}

// ===========================================================================
// HMMA flash attention (fp16 2-term split; K, V single fp16).
//   S = Qhi*K + Qlo*K ; P split hi/lo ; O += Phi*V + Plo*V
// CTA = (64 q rows, head, batch); 4 warps x m16; BN=64; HD=64.
// ===========================================================================
#define FST 72   // smem row stride in halves (144B): conflict-free ldmatrix

__global__ __launch_bounds__(128) void flash_hmma_kernel(
    const __half* __restrict__ Qhi, const __half* __restrict__ Qlo,
    const __half* __restrict__ Khi, const __half* __restrict__ Vhi,
    const int* __restrict__ mask, float* __restrict__ Out)
{
    __shared__ __align__(16) __half KH[64][FST];
    __shared__ __align__(16) __half VH[64][FST];
    __shared__ float MF[64];

    const int t    = threadIdx.x;
    const int lane = t & 31;
    const int warp = t >> 5;
    const int qt   = blockIdx.x;
    const int h    = blockIdx.y;
    const int b    = blockIdx.z;
    const int grow0 = b * L_ + qt * 64;
    const int ghc   = h * HD_;
    const float scale = 0.125f;

    // ---- stage Q tile (hi via KH, lo via VH), read fragments ----
    #pragma unroll
    for (int i = 0; i < 4; i++) {
        int v = t + i * 128;
        int r = v >> 3;
        int c = (v & 7) << 3;
        *reinterpret_cast<uint4*>(&KH[r][c]) =
            *reinterpret_cast<const uint4*>(Qhi + (size_t)(grow0 + r) * D_ + ghc + c);
        *reinterpret_cast<uint4*>(&VH[r][c]) =
            *reinterpret_cast<const uint4*>(Qlo + (size_t)(grow0 + r) * D_ + ghc + c);
    }
    __syncthreads();

    uint32_t qh[4][4], ql[4][4];
    {
        int ar = warp * 16 + (lane & 15);
        int ac = (lane >> 4) << 3;
        #pragma unroll
        for (int kc = 0; kc < 4; kc++) {
            ldsm_x4(qh[kc][0], qh[kc][1], qh[kc][2], qh[kc][3], smem_u32(&KH[ar][kc * 16 + ac]));
            ldsm_x4(ql[kc][0], ql[kc][1], ql[kc][2], ql[kc][3], smem_u32(&VH[ar][kc * 16 + ac]));
        }
    }

    float O[8][4];
    #pragma unroll
    for (int j = 0; j < 8; j++)
        #pragma unroll
        for (int r = 0; r < 4; r++) O[j][r] = 0.0f;
    float m0 = -1e30f, m1 = -1e30f, l0 = 0.0f, l1 = 0.0f;

    for (int kt = 0; kt < 16; kt++) {
        __syncthreads();   // previous-iteration reads done (also covers Q staging)
        const int krow0 = b * L_ + kt * 64;
        #pragma unroll
        for (int i = 0; i < 4; i++) {
            int v = t + i * 128;
            int r = v >> 3;
            int c = (v & 7) << 3;
            size_t gb = (size_t)(krow0 + r) * D_ + ghc + c;
            *reinterpret_cast<uint4*>(&KH[r][c]) = *reinterpret_cast<const uint4*>(Khi + gb);
            *reinterpret_cast<uint4*>(&VH[r][c]) = *reinterpret_cast<const uint4*>(Vhi + gb);
        }
        if (t < 64) MF[t] = mask[b * L_ + kt * 64 + t] ? -1e30f : 0.0f;
        __syncthreads();

        // ---- S = Q K^T (2-term) ----
        float S[8][4];
        #pragma unroll
        for (int j = 0; j < 8; j++) {
            S[j][0] = S[j][1] = S[j][2] = S[j][3] = 0.0f;
            int brow = j * 8 + (lane & 7);
            #pragma unroll
            for (int kc = 0; kc < 4; kc++) {
                int bcol = kc * 16 + (((lane >> 3) & 1) << 3);
                uint32_t bh0, bh1;
                ldsm_x2(bh0, bh1, smem_u32(&KH[brow][bcol]));
                mma_f16(S[j], qh[kc][0], qh[kc][1], qh[kc][2], qh[kc][3], bh0, bh1);
                mma_f16(S[j], ql[kc][0], ql[kc][1], ql[kc][2], ql[kc][3], bh0, bh1);
            }
        }

        // ---- softmax (frag rows l/4, l/4+8; cols 8j+2(l%4)+{0,1}) ----
        float rmax0 = -3.0e38f, rmax1 = -3.0e38f;
        #pragma unroll
        for (int j = 0; j < 8; j++) {
            float ma = MF[j * 8 + ((lane & 3) << 1)];
            float mb = MF[j * 8 + ((lane & 3) << 1) + 1];
            S[j][0] = S[j][0] * scale + ma;
            S[j][1] = S[j][1] * scale + mb;
            S[j][2] = S[j][2] * scale + ma;
            S[j][3] = S[j][3] * scale + mb;
            rmax0 = fmaxf(rmax0, fmaxf(S[j][0], S[j][1]));
            rmax1 = fmaxf(rmax1, fmaxf(S[j][2], S[j][3]));
        }
        rmax0 = fmaxf(rmax0, __shfl_xor_sync(0xffffffffu, rmax0, 1));
        rmax0 = fmaxf(rmax0, __shfl_xor_sync(0xffffffffu, rmax0, 2));
        rmax1 = fmaxf(rmax1, __shfl_xor_sync(0xffffffffu, rmax1, 1));
        rmax1 = fmaxf(rmax1, __shfl_xor_sync(0xffffffffu, rmax1, 2));

        float mn0 = fmaxf(m0, rmax0), mn1 = fmaxf(m1, rmax1);
        float a0 = __expf(m0 - mn0), a1 = __expf(m1 - mn1);
        m0 = mn0; m1 = mn1;

        float sum0 = 0.0f, sum1 = 0.0f;
        #pragma unroll
        for (int j = 0; j < 8; j++) {
            S[j][0] = __expf(S[j][0] - mn0); sum0 += S[j][0];
            S[j][1] = __expf(S[j][1] - mn0); sum0 += S[j][1];
            S[j][2] = __expf(S[j][2] - mn1); sum1 += S[j][2];
            S[j][3] = __expf(S[j][3] - mn1); sum1 += S[j][3];
        }
        sum0 += __shfl_xor_sync(0xffffffffu, sum0, 1);
        sum0 += __shfl_xor_sync(0xffffffffu, sum0, 2);
        sum1 += __shfl_xor_sync(0xffffffffu, sum1, 1);
        sum1 += __shfl_xor_sync(0xffffffffu, sum1, 2);
        l0 = l0 * a0 + sum0;
        l1 = l1 * a1 + sum1;

        #pragma unroll
        for (int j = 0; j < 8; j++) {
            O[j][0] *= a0; O[j][1] *= a0; O[j][2] *= a1; O[j][3] *= a1;
        }

        // ---- split P into hi/lo A-fragments ----
        uint32_t ph[4][4], pl[4][4];
        #pragma unroll
        for (int kc = 0; kc < 4; kc++) {
            const float* x = S[2 * kc];
            const float* y = S[2 * kc + 1];
            __half h0, h1, h2, h3, g0, g1, g2, g3;
            __half e0, e1, e2, e3, f0, f1, f2, f3;
            split2h(x[0], h0, e0); split2h(x[1], h1, e1);
            split2h(x[2], h2, e2); split2h(x[3], h3, e3);
            split2h(y[0], g0, f0); split2h(y[1], g1, f1);
            split2h(y[2], g2, f2); split2h(y[3], g3, f3);
            ph[kc][0] = pack_h(h0, h1); ph[kc][1] = pack_h(h2, h3);
            ph[kc][2] = pack_h(g0, g1); ph[kc][3] = pack_h(g2, g3);
            pl[kc][0] = pack_h(e0, e1); pl[kc][1] = pack_h(e2, e3);
            pl[kc][2] = pack_h(f0, f1); pl[kc][3] = pack_h(f2, f3);
        }

        // ---- O += P V (2-term); V via ldmatrix.trans ----
        #pragma unroll
        for (int jn = 0; jn < 8; jn++) {
            #pragma unroll
            for (int kc = 0; kc < 4; kc++) {
                int vrow = kc * 16 + (lane & 15);
                uint32_t vh0, vh1;
                ldsm_x2t(vh0, vh1, smem_u32(&VH[vrow][jn * 8]));
                mma_f16(O[jn], ph[kc][0], ph[kc][1], ph[kc][2], ph[kc][3], vh0, vh1);
                mma_f16(O[jn], pl[kc][0], pl[kc][1], pl[kc][2], pl[kc][3], vh0, vh1);
            }
        }
    }

    // ---- normalize + write ----
    float inv0 = l0 > 0.0f ? 1.0f / l0 : 0.0f;
    float inv1 = l1 > 0.0f ? 1.0f / l1 : 0.0f;
    int row0 = grow0 + warp * 16 + (lane >> 2);
    int col  = ghc + ((lane & 3) << 1);
    #pragma unroll
    for (int jn = 0; jn < 8; jn++) {
        float2 o0 = { O[jn][0] * inv0, O[jn][1] * inv0 };
        float2 o1 = { O[jn][2] * inv1, O[jn][3] * inv1 };
        *reinterpret_cast<float2*>(Out + (size_t)row0 * D_ + col + jn * 8) = o0;
        *reinterpret_cast<float2*>(Out + (size_t)(row0 + 8) * D_ + col + jn * 8) = o1;
    }
}

// ---------------------------------------------------------------------------
// Launch
// ---------------------------------------------------------------------------
extern "C" void kernel_launch(void* const* d_in, const int* in_sizes, int n_in,
                              void* d_out, int out_size)
{
    const float* query = (const float*)d_in[0];
    const float* key   = (const float*)d_in[1];
    const float* value = (const float*)d_in[2];
    const int*   mask  = (const int*)d_in[3];
    const float* Wq = (const float*)d_in[4];
    const float* bq = (const float*)d_in[5];
    const float* Wk = (const float*)d_in[6];
    const float* bk = (const float*)d_in[7];
    const float* Wv = (const float*)d_in[8];
    const float* bv = (const float*)d_in[9];
    const float* Wo = (const float*)d_in[10];
    const float* bo = (const float*)d_in[11];
    float* out = (float*)d_out;

    void *qh_, *ql_, *kh_, *vh_, *at_;
    cudaGetSymbolAddress(&qh_, g_Qhi); cudaGetSymbolAddress(&ql_, g_Qlo);
    cudaGetSymbolAddress(&kh_, g_Khi); cudaGetSymbolAddress(&vh_, g_Vhi);
    cudaGetSymbolAddress(&at_, g_At);
    __half* Qhi = (__half*)qh_; __half* Qlo = (__half*)ql_;
    __half* Khi = (__half*)kh_; __half* Vhi = (__half*)vh_;
    float* At = (float*)at_;

    dim3 tgrid(D_ / 128, M_TOT / 128);   // (8, 32)

    gemm_hmma_kernel<<<tgrid, 256>>>(query, Wq, bq, nullptr, Qhi, Qlo);
    gemm_hmma_kernel<<<tgrid, 256>>>(key,   Wk, bk, nullptr, Khi, nullptr);
    gemm_hmma_kernel<<<tgrid, 256>>>(value, Wv, bv, nullptr, Vhi, nullptr);

    flash_hmma_kernel<<<dim3(L_ / 64, H_, B_), 128>>>(
        Qhi, Qlo, Khi, Vhi, mask, At);

    gemm_hmma_kernel<<<tgrid, 256>>>(At, Wo, bo, out, nullptr, nullptr);
}

// round 8
// speedup vs baseline: 3.0433x; 1.0053x over previous
#include <cuda_runtime.h>
#include <cuda_fp16.h>
#include <cstdint>

#define B_   4
#define L_   1024
#define D_   1024
#define H_   16
#define HD_  64
#define M_TOT (B_ * L_)   // 4096

// Scratch (static device globals — allocation-guard safe)
__device__ __half g_Qhi[M_TOT * D_];
__device__ __half g_Qlo[M_TOT * D_];
__device__ __half g_Khi[M_TOT * D_];
__device__ __half g_Vhi[M_TOT * D_];
__device__ float  g_At[M_TOT * D_];

// ===========================================================================
// Helpers (baseline ISA: ldmatrix sm_75+, mma.sync fp16 sm_80+)
// ===========================================================================
__device__ __forceinline__ uint32_t smem_u32(const void* p) {
    uint32_t a;
    asm("{ .reg .u64 t; cvta.to.shared.u64 t, %1; cvt.u32.u64 %0, t; }" : "=r"(a) : "l"(p));
    return a;
}
__device__ __forceinline__ void ldsm_x4(uint32_t& r0, uint32_t& r1, uint32_t& r2, uint32_t& r3, uint32_t a) {
    asm volatile("ldmatrix.sync.aligned.m8n8.x4.shared.b16 {%0,%1,%2,%3}, [%4];"
                 : "=r"(r0), "=r"(r1), "=r"(r2), "=r"(r3) : "r"(a));
}
__device__ __forceinline__ void ldsm_x2(uint32_t& r0, uint32_t& r1, uint32_t a) {
    asm volatile("ldmatrix.sync.aligned.m8n8.x2.shared.b16 {%0,%1}, [%2];"
                 : "=r"(r0), "=r"(r1) : "r"(a));
}
__device__ __forceinline__ void ldsm_x2t(uint32_t& r0, uint32_t& r1, uint32_t a) {
    asm volatile("ldmatrix.sync.aligned.m8n8.x2.trans.shared.b16 {%0,%1}, [%2];"
                 : "=r"(r0), "=r"(r1) : "r"(a));
}
__device__ __forceinline__ void mma_f16(float* c,
    uint32_t a0, uint32_t a1, uint32_t a2, uint32_t a3, uint32_t b0, uint32_t b1) {
    asm volatile("mma.sync.aligned.m16n8k16.row.col.f32.f16.f16.f32 "
                 "{%0,%1,%2,%3}, {%4,%5,%6,%7}, {%8,%9}, {%0,%1,%2,%3};"
                 : "+f"(c[0]), "+f"(c[1]), "+f"(c[2]), "+f"(c[3])
                 : "r"(a0), "r"(a1), "r"(a2), "r"(a3), "r"(b0), "r"(b1));
}
__device__ __forceinline__ uint32_t pack_h(__half lo, __half hi) {
    return ((uint32_t)__half_as_ushort(hi) << 16) | __half_as_ushort(lo);
}
__device__ __forceinline__ void split2h(float x, __half& h, __half& l) {
    h = __float2half_rn(x);
    l = __float2half_rn(x - __half2float(h));
}

// ===========================================================================
// HMMA GEMM (fp16 2-term split), double-buffered smem, multi-operand launch.
//   C = A[4096,1024] @ W[1024,1024]^T + bias
//   A split hi/lo fp16; W rounded to fp16. C += Ahi*Whi + Alo*Whi.
// blockIdx.z selects one of 3 operand sets (fused Q/K/V launch).
// ===========================================================================
#define BKC   32
#define NCH   (D_ / BKC)   // 32
#define SST   40
#define ARR_H (128 * SST)              // halves per smem array (5120)
#define STG_H (3 * ARR_H)              // halves per stage (15360)
#define GSMEM (2 * STG_H * 2)          // bytes total (61440)

struct GemmArgs {
    const float* A;
    const float* W;
    const float* bias;
    float*  C;     // fp32 output (if Chi == nullptr)
    __half* Chi;   // hi fp16 output
    __half* Clo;   // lo fp16 output (nullptr -> hi-only)
};

__device__ __forceinline__ void cvt_sts_chunk(
    const float4* pa, const float4* pb, int t,
    __half* ah, __half* al, __half* bh)
{
    #pragma unroll
    for (int i = 0; i < 4; i++) {
        int v = t + i * 256;
        int r = v >> 3;
        int c = (v & 7) << 2;

        float4 a = pa[i];
        __half h0, h1, h2, h3, l0, l1, l2, l3;
        split2h(a.x, h0, l0); split2h(a.y, h1, l1);
        split2h(a.z, h2, l2); split2h(a.w, h3, l3);
        uint2 hv = { pack_h(h0, h1), pack_h(h2, h3) };
        uint2 lv = { pack_h(l0, l1), pack_h(l2, l3) };
        *reinterpret_cast<uint2*>(ah + r * SST + c) = hv;
        *reinterpret_cast<uint2*>(al + r * SST + c) = lv;

        float4 w = pb[i];
        uint2 wv = { pack_h(__float2half_rn(w.x), __float2half_rn(w.y)),
                     pack_h(__float2half_rn(w.z), __float2half_rn(w.w)) };
        *reinterpret_cast<uint2*>(bh + r * SST + c) = wv;
    }
}

__global__ __launch_bounds__(256, 1) void gemm_hmma_multi(
    GemmArgs ga0, GemmArgs ga1, GemmArgs ga2)
{
    extern __shared__ __half dsm[];
    const GemmArgs g = (blockIdx.z == 0) ? ga0 : ((blockIdx.z == 1) ? ga1 : ga2);

    const int t    = threadIdx.x;
    const int lane = t & 31;
    const int warp = t >> 5;
    const int wm   = warp >> 2;
    const int wn   = warp & 3;
    const int m0   = blockIdx.y * 128;
    const int n0   = blockIdx.x * 128;

    const int ldr = (t + 0 * 256) >> 3;       // base row for this thread's LDG slots
    const int ldc = (t & 7) << 2;

    float acc[4][4][4];
    #pragma unroll
    for (int i = 0; i < 4; i++)
        #pragma unroll
        for (int j = 0; j < 4; j++)
            #pragma unroll
            for (int r = 0; r < 4; r++) acc[i][j][r] = 0.0f;

    float4 pa[4], pb[4];
    // prologue: LDG chunk 0, convert to stage 0, LDG chunk 1
    #pragma unroll
    for (int i = 0; i < 4; i++) {
        int r = ldr + i * 32;
        pa[i] = *reinterpret_cast<const float4*>(g.A + (size_t)(m0 + r) * D_ + ldc);
        pb[i] = *reinterpret_cast<const float4*>(g.W + (size_t)(n0 + r) * D_ + ldc);
    }
    cvt_sts_chunk(pa, pb, t, dsm, dsm + ARR_H, dsm + 2 * ARR_H);
    #pragma unroll
    for (int i = 0; i < 4; i++) {
        int r = ldr + i * 32;
        pa[i] = *reinterpret_cast<const float4*>(g.A + (size_t)(m0 + r) * D_ + BKC + ldc);
        pb[i] = *reinterpret_cast<const float4*>(g.W + (size_t)(n0 + r) * D_ + BKC + ldc);
    }
    __syncthreads();

    for (int ck = 0; ck < NCH; ck++) {
        const int st = ck & 1;
        __half* cah = dsm + st * STG_H;
        __half* cal = cah + ARR_H;
        __half* cbh = cah + 2 * ARR_H;

        // fill the other stage with chunk ck+1 (regs), prefetch chunk ck+2
        if (ck + 1 < NCH) {
            __half* nbase = dsm + (st ^ 1) * STG_H;
            cvt_sts_chunk(pa, pb, t, nbase, nbase + ARR_H, nbase + 2 * ARR_H);
            if (ck + 2 < NCH) {
                #pragma unroll
                for (int i = 0; i < 4; i++) {
                    int r = ldr + i * 32;
                    pa[i] = *reinterpret_cast<const float4*>(g.A + (size_t)(m0 + r) * D_ + (ck + 2) * BKC + ldc);
                    pb[i] = *reinterpret_cast<const float4*>(g.W + (size_t)(n0 + r) * D_ + (ck + 2) * BKC + ldc);
                }
            }
        }

        // MMA on current stage
        #pragma unroll
        for (int ks = 0; ks < 2; ks++) {
            const int k0 = ks * 16;
            uint32_t bh[4][2];
            #pragma unroll
            for (int j = 0; j < 4; j++) {
                int row = wn * 32 + j * 8 + (lane & 7);
                int col = k0 + (((lane >> 3) & 1) << 3);
                ldsm_x2(bh[j][0], bh[j][1], smem_u32(cbh + row * SST + col));
            }
            #pragma unroll
            for (int i = 0; i < 4; i++) {
                int row = wm * 64 + i * 16 + (lane & 15);
                int col = k0 + ((lane >> 4) << 3);
                uint32_t ah0, ah1, ah2, ah3, al0, al1, al2, al3;
                ldsm_x4(ah0, ah1, ah2, ah3, smem_u32(cah + row * SST + col));
                ldsm_x4(al0, al1, al2, al3, smem_u32(cal + row * SST + col));
                #pragma unroll
                for (int j = 0; j < 4; j++) {
                    mma_f16(acc[i][j], ah0, ah1, ah2, ah3, bh[j][0], bh[j][1]);
                    mma_f16(acc[i][j], al0, al1, al2, al3, bh[j][0], bh[j][1]);
                }
            }
        }
        __syncthreads();
    }

    const int lr = lane >> 2;
    const int lc = (lane & 3) << 1;
    #pragma unroll
    for (int i = 0; i < 4; i++) {
        #pragma unroll
        for (int j = 0; j < 4; j++) {
            int row = m0 + wm * 64 + i * 16 + lr;
            int col = n0 + wn * 32 + j * 8 + lc;
            float2 bz = *reinterpret_cast<const float2*>(g.bias + col);
            float v0 = acc[i][j][0] + bz.x, v1 = acc[i][j][1] + bz.y;
            float v2 = acc[i][j][2] + bz.x, v3 = acc[i][j][3] + bz.y;
            if (g.Chi) {
                if (g.Clo) {
                    __half h0, h1, h2, h3, l0, l1, l2, l3;
                    split2h(v0, h0, l0); split2h(v1, h1, l1);
                    split2h(v2, h2, l2); split2h(v3, h3, l3);
                    *reinterpret_cast<uint32_t*>(g.Chi + (size_t)row * D_ + col)       = pack_h(h0, h1);
                    *reinterpret_cast<uint32_t*>(g.Clo + (size_t)row * D_ + col)       = pack_h(l0, l1);
                    *reinterpret_cast<uint32_t*>(g.Chi + (size_t)(row + 8) * D_ + col) = pack_h(h2, h3);
                    *reinterpret_cast<uint32_t*>(g.Clo + (size_t)(row + 8) * D_ + col) = pack_h(l2, l3);
                } else {
                    *reinterpret_cast<uint32_t*>(g.Chi + (size_t)row * D_ + col) =
                        pack_h(__float2half_rn(v0), __float2half_rn(v1));
                    *reinterpret_cast<uint32_t*>(g.Chi + (size_t)(row + 8) * D_ + col) =
                        pack_h(__float2half_rn(v2), __float2half_rn(v3));
                }
            } else {
                float2 o0 = { v0, v1 }, o1 = { v2, v3 };
                *reinterpret_cast<float2*>(g.C + (size_t)row * D_ + col) = o0;
                *reinterpret_cast<float2*>(g.C + (size_t)(row + 8) * D_ + col) = o1;
            }
        }
    }
}

// ===========================================================================
// HMMA flash attention (fp16 2-term split; K, V single fp16) — unchanged.
// ===========================================================================
#define FST 72

__global__ __launch_bounds__(128) void flash_hmma_kernel(
    const __half* __restrict__ Qhi, const __half* __restrict__ Qlo,
    const __half* __restrict__ Khi, const __half* __restrict__ Vhi,
    const int* __restrict__ mask, float* __restrict__ Out)
{
    __shared__ __align__(16) __half KH[64][FST];
    __shared__ __align__(16) __half VH[64][FST];
    __shared__ float MF[64];

    const int t    = threadIdx.x;
    const int lane = t & 31;
    const int warp = t >> 5;
    const int qt   = blockIdx.x;
    const int h    = blockIdx.y;
    const int b    = blockIdx.z;
    const int grow0 = b * L_ + qt * 64;
    const int ghc   = h * HD_;
    const float scale = 0.125f;

    #pragma unroll
    for (int i = 0; i < 4; i++) {
        int v = t + i * 128;
        int r = v >> 3;
        int c = (v & 7) << 3;
        *reinterpret_cast<uint4*>(&KH[r][c]) =
            *reinterpret_cast<const uint4*>(Qhi + (size_t)(grow0 + r) * D_ + ghc + c);
        *reinterpret_cast<uint4*>(&VH[r][c]) =
            *reinterpret_cast<const uint4*>(Qlo + (size_t)(grow0 + r) * D_ + ghc + c);
    }
    __syncthreads();

    uint32_t qh[4][4], ql[4][4];
    {
        int ar = warp * 16 + (lane & 15);
        int ac = (lane >> 4) << 3;
        #pragma unroll
        for (int kc = 0; kc < 4; kc++) {
            ldsm_x4(qh[kc][0], qh[kc][1], qh[kc][2], qh[kc][3], smem_u32(&KH[ar][kc * 16 + ac]));
            ldsm_x4(ql[kc][0], ql[kc][1], ql[kc][2], ql[kc][3], smem_u32(&VH[ar][kc * 16 + ac]));
        }
    }

    float O[8][4];
    #pragma unroll
    for (int j = 0; j < 8; j++)
        #pragma unroll
        for (int r = 0; r < 4; r++) O[j][r] = 0.0f;
    float m0 = -1e30f, m1 = -1e30f, l0 = 0.0f, l1 = 0.0f;

    for (int kt = 0; kt < 16; kt++) {
        __syncthreads();
        const int krow0 = b * L_ + kt * 64;
        #pragma unroll
        for (int i = 0; i < 4; i++) {
            int v = t + i * 128;
            int r = v >> 3;
            int c = (v & 7) << 3;
            size_t gb = (size_t)(krow0 + r) * D_ + ghc + c;
            *reinterpret_cast<uint4*>(&KH[r][c]) = *reinterpret_cast<const uint4*>(Khi + gb);
            *reinterpret_cast<uint4*>(&VH[r][c]) = *reinterpret_cast<const uint4*>(Vhi + gb);
        }
        if (t < 64) MF[t] = mask[b * L_ + kt * 64 + t] ? -1e30f : 0.0f;
        __syncthreads();

        float S[8][4];
        #pragma unroll
        for (int j = 0; j < 8; j++) {
            S[j][0] = S[j][1] = S[j][2] = S[j][3] = 0.0f;
            int brow = j * 8 + (lane & 7);
            #pragma unroll
            for (int kc = 0; kc < 4; kc++) {
                int bcol = kc * 16 + (((lane >> 3) & 1) << 3);
                uint32_t bh0, bh1;
                ldsm_x2(bh0, bh1, smem_u32(&KH[brow][bcol]));
                mma_f16(S[j], qh[kc][0], qh[kc][1], qh[kc][2], qh[kc][3], bh0, bh1);
                mma_f16(S[j], ql[kc][0], ql[kc][1], ql[kc][2], ql[kc][3], bh0, bh1);
            }
        }

        float rmax0 = -3.0e38f, rmax1 = -3.0e38f;
        #pragma unroll
        for (int j = 0; j < 8; j++) {
            float ma = MF[j * 8 + ((lane & 3) << 1)];
            float mb = MF[j * 8 + ((lane & 3) << 1) + 1];
            S[j][0] = S[j][0] * scale + ma;
            S[j][1] = S[j][1] * scale + mb;
            S[j][2] = S[j][2] * scale + ma;
            S[j][3] = S[j][3] * scale + mb;
            rmax0 = fmaxf(rmax0, fmaxf(S[j][0], S[j][1]));
            rmax1 = fmaxf(rmax1, fmaxf(S[j][2], S[j][3]));
        }
        rmax0 = fmaxf(rmax0, __shfl_xor_sync(0xffffffffu, rmax0, 1));
        rmax0 = fmaxf(rmax0, __shfl_xor_sync(0xffffffffu, rmax0, 2));
        rmax1 = fmaxf(rmax1, __shfl_xor_sync(0xffffffffu, rmax1, 1));
        rmax1 = fmaxf(rmax1, __shfl_xor_sync(0xffffffffu, rmax1, 2));

        float mn0 = fmaxf(m0, rmax0), mn1 = fmaxf(m1, rmax1);
        float a0 = __expf(m0 - mn0), a1 = __expf(m1 - mn1);
        m0 = mn0; m1 = mn1;

        float sum0 = 0.0f, sum1 = 0.0f;
        #pragma unroll
        for (int j = 0; j < 8; j++) {
            S[j][0] = __expf(S[j][0] - mn0); sum0 += S[j][0];
            S[j][1] = __expf(S[j][1] - mn0); sum0 += S[j][1];
            S[j][2] = __expf(S[j][2] - mn1); sum1 += S[j][2];
            S[j][3] = __expf(S[j][3] - mn1); sum1 += S[j][3];
        }
        sum0 += __shfl_xor_sync(0xffffffffu, sum0, 1);
        sum0 += __shfl_xor_sync(0xffffffffu, sum0, 2);
        sum1 += __shfl_xor_sync(0xffffffffu, sum1, 1);
        sum1 += __shfl_xor_sync(0xffffffffu, sum1, 2);
        l0 = l0 * a0 + sum0;
        l1 = l1 * a1 + sum1;

        #pragma unroll
        for (int j = 0; j < 8; j++) {
            O[j][0] *= a0; O[j][1] *= a0; O[j][2] *= a1; O[j][3] *= a1;
        }

        uint32_t ph[4][4], pl[4][4];
        #pragma unroll
        for (int kc = 0; kc < 4; kc++) {
            const float* x = S[2 * kc];
            const float* y = S[2 * kc + 1];
            __half h0, h1, h2, h3, g0, g1, g2, g3;
            __half e0, e1, e2, e3, f0, f1, f2, f3;
            split2h(x[0], h0, e0); split2h(x[1], h1, e1);
            split2h(x[2], h2, e2); split2h(x[3], h3, e3);
            split2h(y[0], g0, f0); split2h(y[1], g1, f1);
            split2h(y[2], g2, f2); split2h(y[3], g3, f3);
            ph[kc][0] = pack_h(h0, h1); ph[kc][1] = pack_h(h2, h3);
            ph[kc][2] = pack_h(g0, g1); ph[kc][3] = pack_h(g2, g3);
            pl[kc][0] = pack_h(e0, e1); pl[kc][1] = pack_h(e2, e3);
            pl[kc][2] = pack_h(f0, f1); pl[kc][3] = pack_h(f2, f3);
        }

        #pragma unroll
        for (int jn = 0; jn < 8; jn++) {
            #pragma unroll
            for (int kc = 0; kc < 4; kc++) {
                int vrow = kc * 16 + (lane & 15);
                uint32_t vh0, vh1;
                ldsm_x2t(vh0, vh1, smem_u32(&VH[vrow][jn * 8]));
                mma_f16(O[jn], ph[kc][0], ph[kc][1], ph[kc][2], ph[kc][3], vh0, vh1);
                mma_f16(O[jn], pl[kc][0], pl[kc][1], pl[kc][2], pl[kc][3], vh0, vh1);
            }
        }
    }

    float inv0 = l0 > 0.0f ? 1.0f / l0 : 0.0f;
    float inv1 = l1 > 0.0f ? 1.0f / l1 : 0.0f;
    int row0 = grow0 + warp * 16 + (lane >> 2);
    int col  = ghc + ((lane & 3) << 1);
    #pragma unroll
    for (int jn = 0; jn < 8; jn++) {
        float2 o0 = { O[jn][0] * inv0, O[jn][1] * inv0 };
        float2 o1 = { O[jn][2] * inv1, O[jn][3] * inv1 };
        *reinterpret_cast<float2*>(Out + (size_t)row0 * D_ + col + jn * 8) = o0;
        *reinterpret_cast<float2*>(Out + (size_t)(row0 + 8) * D_ + col + jn * 8) = o1;
    }
}

// ---------------------------------------------------------------------------
// Launch
// ---------------------------------------------------------------------------
extern "C" void kernel_launch(void* const* d_in, const int* in_sizes, int n_in,
                              void* d_out, int out_size)
{
    const float* query = (const float*)d_in[0];
    const float* key   = (const float*)d_in[1];
    const float* value = (const float*)d_in[2];
    const int*   mask  = (const int*)d_in[3];
    const float* Wq = (const float*)d_in[4];
    const float* bq = (const float*)d_in[5];
    const float* Wk = (const float*)d_in[6];
    const float* bk = (const float*)d_in[7];
    const float* Wv = (const float*)d_in[8];
    const float* bv = (const float*)d_in[9];
    const float* Wo = (const float*)d_in[10];
    const float* bo = (const float*)d_in[11];
    float* out = (float*)d_out;

    void *qh_, *ql_, *kh_, *vh_, *at_;
    cudaGetSymbolAddress(&qh_, g_Qhi); cudaGetSymbolAddress(&ql_, g_Qlo);
    cudaGetSymbolAddress(&kh_, g_Khi); cudaGetSymbolAddress(&vh_, g_Vhi);
    cudaGetSymbolAddress(&at_, g_At);
    __half* Qhi = (__half*)qh_; __half* Qlo = (__half*)ql_;
    __half* Khi = (__half*)kh_; __half* Vhi = (__half*)vh_;
    float* At = (float*)at_;

    cudaFuncSetAttribute(gemm_hmma_multi,
                         cudaFuncAttributeMaxDynamicSharedMemorySize, GSMEM);

    GemmArgs qa = { query, Wq, bq, nullptr, Qhi, Qlo };
    GemmArgs ka = { key,   Wk, bk, nullptr, Khi, nullptr };
    GemmArgs va = { value, Wv, bv, nullptr, Vhi, nullptr };
    GemmArgs oa = { At,    Wo, bo, out,     nullptr, nullptr };

    // fused Q/K/V projections (z selects operand set)
    gemm_hmma_multi<<<dim3(D_ / 128, M_TOT / 128, 3), 256, GSMEM>>>(qa, ka, va);

    flash_hmma_kernel<<<dim3(L_ / 64, H_, B_), 128>>>(
        Qhi, Qlo, Khi, Vhi, mask, At);

    // output projection
    gemm_hmma_multi<<<dim3(D_ / 128, M_TOT / 128, 1), 256, GSMEM>>>(oa, oa, oa);
}

// round 9
// speedup vs baseline: 3.6088x; 1.1858x over previous
#include <cuda_runtime.h>
#include <cuda_fp16.h>
#include <cstdint>

#define B_   4
#define L_   1024
#define D_   1024
#define H_   16
#define HD_  64
#define M_TOT (B_ * L_)   // 4096

// Scratch (static device globals — allocation-guard safe)
__device__ __half g_Iqh[M_TOT * D_], g_Iql[M_TOT * D_];   // input splits
__device__ __half g_Ikh[M_TOT * D_], g_Ikl[M_TOT * D_];
__device__ __half g_Ivh[M_TOT * D_], g_Ivl[M_TOT * D_];
__device__ __half g_Wq16[D_ * D_], g_Wk16[D_ * D_], g_Wv16[D_ * D_], g_Wo16[D_ * D_];
__device__ __half g_Qhi[M_TOT * D_], g_Qlo[M_TOT * D_];   // projected
__device__ __half g_Khi[M_TOT * D_], g_Vhi[M_TOT * D_];
__device__ __half g_Athi[M_TOT * D_], g_Atlo[M_TOT * D_]; // attention out split

// ===========================================================================
// Helpers
// ===========================================================================
__device__ __forceinline__ uint32_t smem_u32(const void* p) {
    uint32_t a;
    asm("{ .reg .u64 t; cvta.to.shared.u64 t, %1; cvt.u32.u64 %0, t; }" : "=r"(a) : "l"(p));
    return a;
}
__device__ __forceinline__ void ldsm_x4(uint32_t& r0, uint32_t& r1, uint32_t& r2, uint32_t& r3, uint32_t a) {
    asm volatile("ldmatrix.sync.aligned.m8n8.x4.shared.b16 {%0,%1,%2,%3}, [%4];"
                 : "=r"(r0), "=r"(r1), "=r"(r2), "=r"(r3) : "r"(a));
}
__device__ __forceinline__ void ldsm_x2(uint32_t& r0, uint32_t& r1, uint32_t a) {
    asm volatile("ldmatrix.sync.aligned.m8n8.x2.shared.b16 {%0,%1}, [%2];"
                 : "=r"(r0), "=r"(r1) : "r"(a));
}
__device__ __forceinline__ void ldsm_x2t(uint32_t& r0, uint32_t& r1, uint32_t a) {
    asm volatile("ldmatrix.sync.aligned.m8n8.x2.trans.shared.b16 {%0,%1}, [%2];"
                 : "=r"(r0), "=r"(r1) : "r"(a));
}
__device__ __forceinline__ void mma_f16(float* c,
    uint32_t a0, uint32_t a1, uint32_t a2, uint32_t a3, uint32_t b0, uint32_t b1) {
    asm volatile("mma.sync.aligned.m16n8k16.row.col.f32.f16.f16.f32 "
                 "{%0,%1,%2,%3}, {%4,%5,%6,%7}, {%8,%9}, {%0,%1,%2,%3};"
                 : "+f"(c[0]), "+f"(c[1]), "+f"(c[2]), "+f"(c[3])
                 : "r"(a0), "r"(a1), "r"(a2), "r"(a3), "r"(b0), "r"(b1));
}
__device__ __forceinline__ uint32_t pack_h(__half lo, __half hi) {
    return ((uint32_t)__half_as_ushort(hi) << 16) | __half_as_ushort(lo);
}
__device__ __forceinline__ void split2h(float x, __half& h, __half& l) {
    h = __float2half_rn(x);
    l = __float2half_rn(x - __half2float(h));
}
__device__ __forceinline__ void cp16(uint32_t dst, const void* src) {
    asm volatile("cp.async.cg.shared.global [%0], [%1], 16;" :: "r"(dst), "l"(src));
}
__device__ __forceinline__ void cp_commit() { asm volatile("cp.async.commit_group;"); }
template<int N> __device__ __forceinline__ void cp_wait() {
    asm volatile("cp.async.wait_group %0;" :: "n"(N));
}

// ===========================================================================
// Prep: split inputs to hi/lo fp16; round weights to fp16.  grid (512,1,7)
// ===========================================================================
__global__ __launch_bounds__(256) void prep_kernel(
    const float* __restrict__ q, const float* __restrict__ k, const float* __restrict__ v,
    const float* __restrict__ wq, const float* __restrict__ wk,
    const float* __restrict__ wv, const float* __restrict__ wo,
    __half* qh, __half* ql, __half* kh, __half* kl, __half* vh, __half* vl,
    __half* wqh, __half* wkh, __half* wvh, __half* woh)
{
    const int z = blockIdx.z;
    const int base = blockIdx.x * 256 + threadIdx.x;
    if (z < 3) {
        const float* src = (z == 0) ? q : (z == 1) ? k : v;
        __half* dh = (z == 0) ? qh : (z == 1) ? kh : vh;
        __half* dl = (z == 0) ? ql : (z == 1) ? kl : vl;
        #pragma unroll
        for (int i = 0; i < 8; i++) {
            int e4 = base + i * 131072;
            float4 x = reinterpret_cast<const float4*>(src)[e4];
            __half h0, h1, h2, h3, l0, l1, l2, l3;
            split2h(x.x, h0, l0); split2h(x.y, h1, l1);
            split2h(x.z, h2, l2); split2h(x.w, h3, l3);
            uint2 hv = { pack_h(h0, h1), pack_h(h2, h3) };
            uint2 lv = { pack_h(l0, l1), pack_h(l2, l3) };
            *reinterpret_cast<uint2*>(dh + (size_t)e4 * 4) = hv;
            *reinterpret_cast<uint2*>(dl + (size_t)e4 * 4) = lv;
        }
    } else {
        const float* src = (z == 3) ? wq : (z == 4) ? wk : (z == 5) ? wv : wo;
        __half* dst = (z == 3) ? wqh : (z == 4) ? wkh : (z == 5) ? wvh : woh;
        #pragma unroll
        for (int i = 0; i < 2; i++) {
            int e4 = base + i * 131072;
            float4 x = reinterpret_cast<const float4*>(src)[e4];
            uint2 wv2 = { pack_h(__float2half_rn(x.x), __float2half_rn(x.y)),
                          pack_h(__float2half_rn(x.z), __float2half_rn(x.w)) };
            *reinterpret_cast<uint2*>(dst + (size_t)e4 * 4) = wv2;
        }
    }
}

// ===========================================================================
// Pure-fp16 HMMA GEMM, cp.async double-buffered.
//   C = (Ah + Al) @ Wh^T + bias   (fp32 accum)
// ===========================================================================
#define BKC   32
#define NCH   (D_ / BKC)   // 32
#define SST   40
#define ARR_H (128 * SST)              // halves per array (5120)
#define STG_H (3 * ARR_H)              // halves per stage
#define GSMEM (2 * STG_H * 2)          // 61440 bytes

struct GemmArgs {
    const __half* Ah;
    const __half* Al;
    const __half* Wh;
    const float*  bias;
    float*  C;     // fp32 out (if Chi == nullptr)
    __half* Chi;   // hi fp16 out
    __half* Clo;   // lo fp16 out (nullptr -> hi-only)
};

__device__ __forceinline__ void issue_chunk(
    const GemmArgs& g, int m0, int n0, int k0, int t, uint32_t stage_b)
{
    #pragma unroll
    for (int i = 0; i < 2; i++) {
        int s  = t + (i << 8);
        int r  = s >> 2;
        int c8 = (s & 3) << 3;
        uint32_t d = stage_b + (uint32_t)(r * SST + c8) * 2;
        size_t goff = (size_t)(m0 + r) * D_ + k0 + c8;
        cp16(d,                 g.Ah + goff);
        cp16(d + ARR_H * 2,     g.Al + goff);
        cp16(d + 2 * ARR_H * 2, g.Wh + (size_t)(n0 + r) * D_ + k0 + c8);
    }
}

__global__ __launch_bounds__(256, 2) void gemm_f16_multi(
    GemmArgs ga0, GemmArgs ga1, GemmArgs ga2)
{
    extern __shared__ __half dsm[];
    const GemmArgs g = (blockIdx.z == 0) ? ga0 : ((blockIdx.z == 1) ? ga1 : ga2);

    const int t    = threadIdx.x;
    const int lane = t & 31;
    const int warp = t >> 5;
    const int wm   = warp >> 2;
    const int wn   = warp & 3;
    const int m0   = blockIdx.y * 128;
    const int n0   = blockIdx.x * 128;
    const uint32_t sb = smem_u32(dsm);

    float acc[4][4][4];
    #pragma unroll
    for (int i = 0; i < 4; i++)
        #pragma unroll
        for (int j = 0; j < 4; j++)
            #pragma unroll
            for (int r = 0; r < 4; r++) acc[i][j][r] = 0.0f;

    issue_chunk(g, m0, n0, 0, t, sb);
    cp_commit();
    issue_chunk(g, m0, n0, BKC, t, sb + STG_H * 2);
    cp_commit();

    for (int ck = 0; ck < NCH; ck++) {
        const int st = ck & 1;
        const __half* cah = dsm + st * STG_H;
        const __half* cal = cah + ARR_H;
        const __half* cbh = cah + 2 * ARR_H;

        if (ck + 1 < NCH) cp_wait<1>(); else cp_wait<0>();
        __syncthreads();

        #pragma unroll
        for (int ks = 0; ks < 2; ks++) {
            const int k0 = ks * 16;
            uint32_t bh[4][2];
            #pragma unroll
            for (int j = 0; j < 4; j++) {
                int row = wn * 32 + j * 8 + (lane & 7);
                int col = k0 + (((lane >> 3) & 1) << 3);
                ldsm_x2(bh[j][0], bh[j][1], smem_u32(cbh + row * SST + col));
            }
            #pragma unroll
            for (int i = 0; i < 4; i++) {
                int row = wm * 64 + i * 16 + (lane & 15);
                int col = k0 + ((lane >> 4) << 3);
                uint32_t ah0, ah1, ah2, ah3, al0, al1, al2, al3;
                ldsm_x4(ah0, ah1, ah2, ah3, smem_u32(cah + row * SST + col));
                ldsm_x4(al0, al1, al2, al3, smem_u32(cal + row * SST + col));
                #pragma unroll
                for (int j = 0; j < 4; j++) {
                    mma_f16(acc[i][j], ah0, ah1, ah2, ah3, bh[j][0], bh[j][1]);
                    mma_f16(acc[i][j], al0, al1, al2, al3, bh[j][0], bh[j][1]);
                }
            }
        }
        __syncthreads();

        if (ck + 2 < NCH) {
            issue_chunk(g, m0, n0, (ck + 2) * BKC, t, sb + st * STG_H * 2);
            cp_commit();
        }
    }

    const int lr = lane >> 2;
    const int lc = (lane & 3) << 1;
    #pragma unroll
    for (int i = 0; i < 4; i++) {
        #pragma unroll
        for (int j = 0; j < 4; j++) {
            int row = m0 + wm * 64 + i * 16 + lr;
            int col = n0 + wn * 32 + j * 8 + lc;
            float2 bz = *reinterpret_cast<const float2*>(g.bias + col);
            float v0 = acc[i][j][0] + bz.x, v1 = acc[i][j][1] + bz.y;
            float v2 = acc[i][j][2] + bz.x, v3 = acc[i][j][3] + bz.y;
            if (g.Chi) {
                if (g.Clo) {
                    __half h0, h1, h2, h3, l0, l1, l2, l3;
                    split2h(v0, h0, l0); split2h(v1, h1, l1);
                    split2h(v2, h2, l2); split2h(v3, h3, l3);
                    *reinterpret_cast<uint32_t*>(g.Chi + (size_t)row * D_ + col)       = pack_h(h0, h1);
                    *reinterpret_cast<uint32_t*>(g.Clo + (size_t)row * D_ + col)       = pack_h(l0, l1);
                    *reinterpret_cast<uint32_t*>(g.Chi + (size_t)(row + 8) * D_ + col) = pack_h(h2, h3);
                    *reinterpret_cast<uint32_t*>(g.Clo + (size_t)(row + 8) * D_ + col) = pack_h(l2, l3);
                } else {
                    *reinterpret_cast<uint32_t*>(g.Chi + (size_t)row * D_ + col) =
                        pack_h(__float2half_rn(v0), __float2half_rn(v1));
                    *reinterpret_cast<uint32_t*>(g.Chi + (size_t)(row + 8) * D_ + col) =
                        pack_h(__float2half_rn(v2), __float2half_rn(v3));
                }
            } else {
                float2 o0 = { v0, v1 }, o1 = { v2, v3 };
                *reinterpret_cast<float2*>(g.C + (size_t)row * D_ + col) = o0;
                *reinterpret_cast<float2*>(g.C + (size_t)(row + 8) * D_ + col) = o1;
            }
        }
    }
}

// ===========================================================================
// HMMA flash attention (fp16 2-term split; K, V single fp16).
// Epilogue writes At as hi/lo fp16 (feeds O-projection directly).
// ===========================================================================
#define FST 72

__global__ __launch_bounds__(128) void flash_hmma_kernel(
    const __half* __restrict__ Qhi, const __half* __restrict__ Qlo,
    const __half* __restrict__ Khi, const __half* __restrict__ Vhi,
    const int* __restrict__ mask,
    __half* __restrict__ Oh, __half* __restrict__ Ol)
{
    __shared__ __align__(16) __half KH[64][FST];
    __shared__ __align__(16) __half VH[64][FST];
    __shared__ float MF[64];

    const int t    = threadIdx.x;
    const int lane = t & 31;
    const int warp = t >> 5;
    const int qt   = blockIdx.x;
    const int h    = blockIdx.y;
    const int b    = blockIdx.z;
    const int grow0 = b * L_ + qt * 64;
    const int ghc   = h * HD_;
    const float scale = 0.125f;

    #pragma unroll
    for (int i = 0; i < 4; i++) {
        int v = t + i * 128;
        int r = v >> 3;
        int c = (v & 7) << 3;
        *reinterpret_cast<uint4*>(&KH[r][c]) =
            *reinterpret_cast<const uint4*>(Qhi + (size_t)(grow0 + r) * D_ + ghc + c);
        *reinterpret_cast<uint4*>(&VH[r][c]) =
            *reinterpret_cast<const uint4*>(Qlo + (size_t)(grow0 + r) * D_ + ghc + c);
    }
    __syncthreads();

    uint32_t qh[4][4], ql[4][4];
    {
        int ar = warp * 16 + (lane & 15);
        int ac = (lane >> 4) << 3;
        #pragma unroll
        for (int kc = 0; kc < 4; kc++) {
            ldsm_x4(qh[kc][0], qh[kc][1], qh[kc][2], qh[kc][3], smem_u32(&KH[ar][kc * 16 + ac]));
            ldsm_x4(ql[kc][0], ql[kc][1], ql[kc][2], ql[kc][3], smem_u32(&VH[ar][kc * 16 + ac]));
        }
    }

    float O[8][4];
    #pragma unroll
    for (int j = 0; j < 8; j++)
        #pragma unroll
        for (int r = 0; r < 4; r++) O[j][r] = 0.0f;
    float m0 = -1e30f, m1 = -1e30f, l0 = 0.0f, l1 = 0.0f;

    for (int kt = 0; kt < 16; kt++) {
        __syncthreads();
        const int krow0 = b * L_ + kt * 64;
        #pragma unroll
        for (int i = 0; i < 4; i++) {
            int v = t + i * 128;
            int r = v >> 3;
            int c = (v & 7) << 3;
            size_t gb = (size_t)(krow0 + r) * D_ + ghc + c;
            *reinterpret_cast<uint4*>(&KH[r][c]) = *reinterpret_cast<const uint4*>(Khi + gb);
            *reinterpret_cast<uint4*>(&VH[r][c]) = *reinterpret_cast<const uint4*>(Vhi + gb);
        }
        if (t < 64) MF[t] = mask[b * L_ + kt * 64 + t] ? -1e30f : 0.0f;
        __syncthreads();

        float S[8][4];
        #pragma unroll
        for (int j = 0; j < 8; j++) {
            S[j][0] = S[j][1] = S[j][2] = S[j][3] = 0.0f;
            int brow = j * 8 + (lane & 7);
            #pragma unroll
            for (int kc = 0; kc < 4; kc++) {
                int bcol = kc * 16 + (((lane >> 3) & 1) << 3);
                uint32_t bh0, bh1;
                ldsm_x2(bh0, bh1, smem_u32(&KH[brow][bcol]));
                mma_f16(S[j], qh[kc][0], qh[kc][1], qh[kc][2], qh[kc][3], bh0, bh1);
                mma_f16(S[j], ql[kc][0], ql[kc][1], ql[kc][2], ql[kc][3], bh0, bh1);
            }
        }

        float rmax0 = -3.0e38f, rmax1 = -3.0e38f;
        #pragma unroll
        for (int j = 0; j < 8; j++) {
            float ma = MF[j * 8 + ((lane & 3) << 1)];
            float mb = MF[j * 8 + ((lane & 3) << 1) + 1];
            S[j][0] = S[j][0] * scale + ma;
            S[j][1] = S[j][1] * scale + mb;
            S[j][2] = S[j][2] * scale + ma;
            S[j][3] = S[j][3] * scale + mb;
            rmax0 = fmaxf(rmax0, fmaxf(S[j][0], S[j][1]));
            rmax1 = fmaxf(rmax1, fmaxf(S[j][2], S[j][3]));
        }
        rmax0 = fmaxf(rmax0, __shfl_xor_sync(0xffffffffu, rmax0, 1));
        rmax0 = fmaxf(rmax0, __shfl_xor_sync(0xffffffffu, rmax0, 2));
        rmax1 = fmaxf(rmax1, __shfl_xor_sync(0xffffffffu, rmax1, 1));
        rmax1 = fmaxf(rmax1, __shfl_xor_sync(0xffffffffu, rmax1, 2));

        float mn0 = fmaxf(m0, rmax0), mn1 = fmaxf(m1, rmax1);
        float a0 = __expf(m0 - mn0), a1 = __expf(m1 - mn1);
        m0 = mn0; m1 = mn1;

        float sum0 = 0.0f, sum1 = 0.0f;
        #pragma unroll
        for (int j = 0; j < 8; j++) {
            S[j][0] = __expf(S[j][0] - mn0); sum0 += S[j][0];
            S[j][1] = __expf(S[j][1] - mn0); sum0 += S[j][1];
            S[j][2] = __expf(S[j][2] - mn1); sum1 += S[j][2];
            S[j][3] = __expf(S[j][3] - mn1); sum1 += S[j][3];
        }
        sum0 += __shfl_xor_sync(0xffffffffu, sum0, 1);
        sum0 += __shfl_xor_sync(0xffffffffu, sum0, 2);
        sum1 += __shfl_xor_sync(0xffffffffu, sum1, 1);
        sum1 += __shfl_xor_sync(0xffffffffu, sum1, 2);
        l0 = l0 * a0 + sum0;
        l1 = l1 * a1 + sum1;

        #pragma unroll
        for (int j = 0; j < 8; j++) {
            O[j][0] *= a0; O[j][1] *= a0; O[j][2] *= a1; O[j][3] *= a1;
        }

        uint32_t ph[4][4], pl[4][4];
        #pragma unroll
        for (int kc = 0; kc < 4; kc++) {
            const float* x = S[2 * kc];
            const float* y = S[2 * kc + 1];
            __half h0, h1, h2, h3, g0, g1, g2, g3;
            __half e0, e1, e2, e3, f0, f1, f2, f3;
            split2h(x[0], h0, e0); split2h(x[1], h1, e1);
            split2h(x[2], h2, e2); split2h(x[3], h3, e3);
            split2h(y[0], g0, f0); split2h(y[1], g1, f1);
            split2h(y[2], g2, f2); split2h(y[3], g3, f3);
            ph[kc][0] = pack_h(h0, h1); ph[kc][1] = pack_h(h2, h3);
            ph[kc][2] = pack_h(g0, g1); ph[kc][3] = pack_h(g2, g3);
            pl[kc][0] = pack_h(e0, e1); pl[kc][1] = pack_h(e2, e3);
            pl[kc][2] = pack_h(f0, f1); pl[kc][3] = pack_h(f2, f3);
        }

        #pragma unroll
        for (int jn = 0; jn < 8; jn++) {
            #pragma unroll
            for (int kc = 0; kc < 4; kc++) {
                int vrow = kc * 16 + (lane & 15);
                uint32_t vh0, vh1;
                ldsm_x2t(vh0, vh1, smem_u32(&VH[vrow][jn * 8]));
                mma_f16(O[jn], ph[kc][0], ph[kc][1], ph[kc][2], ph[kc][3], vh0, vh1);
                mma_f16(O[jn], pl[kc][0], pl[kc][1], pl[kc][2], pl[kc][3], vh0, vh1);
            }
        }
    }

    float inv0 = l0 > 0.0f ? 1.0f / l0 : 0.0f;
    float inv1 = l1 > 0.0f ? 1.0f / l1 : 0.0f;
    int row0 = grow0 + warp * 16 + (lane >> 2);
    int col  = ghc + ((lane & 3) << 1);
    #pragma unroll
    for (int jn = 0; jn < 8; jn++) {
        float x0 = O[jn][0] * inv0, x1 = O[jn][1] * inv0;
        float x2 = O[jn][2] * inv1, x3 = O[jn][3] * inv1;
        __half h0, h1, h2, h3, e0, e1, e2, e3;
        split2h(x0, h0, e0); split2h(x1, h1, e1);
        split2h(x2, h2, e2); split2h(x3, h3, e3);
        *reinterpret_cast<uint32_t*>(Oh + (size_t)row0 * D_ + col + jn * 8)       = pack_h(h0, h1);
        *reinterpret_cast<uint32_t*>(Ol + (size_t)row0 * D_ + col + jn * 8)       = pack_h(e0, e1);
        *reinterpret_cast<uint32_t*>(Oh + (size_t)(row0 + 8) * D_ + col + jn * 8) = pack_h(h2, h3);
        *reinterpret_cast<uint32_t*>(Ol + (size_t)(row0 + 8) * D_ + col + jn * 8) = pack_h(e2, e3);
    }
}

// ---------------------------------------------------------------------------
// Launch
// ---------------------------------------------------------------------------
extern "C" void kernel_launch(void* const* d_in, const int* in_sizes, int n_in,
                              void* d_out, int out_size)
{
    const float* query = (const float*)d_in[0];
    const float* key   = (const float*)d_in[1];
    const float* value = (const float*)d_in[2];
    const int*   mask  = (const int*)d_in[3];
    const float* Wq = (const float*)d_in[4];
    const float* bq = (const float*)d_in[5];
    const float* Wk = (const float*)d_in[6];
    const float* bk = (const float*)d_in[7];
    const float* Wv = (const float*)d_in[8];
    const float* bv = (const float*)d_in[9];
    const float* Wo = (const float*)d_in[10];
    const float* bo = (const float*)d_in[11];
    float* out = (float*)d_out;

    void *p[16];
    cudaGetSymbolAddress(&p[0],  g_Iqh);  cudaGetSymbolAddress(&p[1],  g_Iql);
    cudaGetSymbolAddress(&p[2],  g_Ikh);  cudaGetSymbolAddress(&p[3],  g_Ikl);
    cudaGetSymbolAddress(&p[4],  g_Ivh);  cudaGetSymbolAddress(&p[5],  g_Ivl);
    cudaGetSymbolAddress(&p[6],  g_Wq16); cudaGetSymbolAddress(&p[7],  g_Wk16);
    cudaGetSymbolAddress(&p[8],  g_Wv16); cudaGetSymbolAddress(&p[9],  g_Wo16);
    cudaGetSymbolAddress(&p[10], g_Qhi);  cudaGetSymbolAddress(&p[11], g_Qlo);
    cudaGetSymbolAddress(&p[12], g_Khi);  cudaGetSymbolAddress(&p[13], g_Vhi);
    cudaGetSymbolAddress(&p[14], g_Athi); cudaGetSymbolAddress(&p[15], g_Atlo);
    __half* Iqh = (__half*)p[0];  __half* Iql = (__half*)p[1];
    __half* Ikh = (__half*)p[2];  __half* Ikl = (__half*)p[3];
    __half* Ivh = (__half*)p[4];  __half* Ivl = (__half*)p[5];
    __half* Wq16 = (__half*)p[6]; __half* Wk16 = (__half*)p[7];
    __half* Wv16 = (__half*)p[8]; __half* Wo16 = (__half*)p[9];
    __half* Qhi = (__half*)p[10]; __half* Qlo = (__half*)p[11];
    __half* Khi = (__half*)p[12]; __half* Vhi = (__half*)p[13];
    __half* Athi = (__half*)p[14]; __half* Atlo = (__half*)p[15];

    cudaFuncSetAttribute(gemm_f16_multi,
                         cudaFuncAttributeMaxDynamicSharedMemorySize, GSMEM);

    prep_kernel<<<dim3(512, 1, 7), 256>>>(
        query, key, value, Wq, Wk, Wv, Wo,
        Iqh, Iql, Ikh, Ikl, Ivh, Ivl, Wq16, Wk16, Wv16, Wo16);

    GemmArgs qa = { Iqh, Iql, Wq16, bq, nullptr, Qhi, Qlo };
    GemmArgs ka = { Ikh, Ikl, Wk16, bk, nullptr, Khi, nullptr };
    GemmArgs va = { Ivh, Ivl, Wv16, bv, nullptr, Vhi, nullptr };
    GemmArgs oa = { Athi, Atlo, Wo16, bo, out, nullptr, nullptr };

    gemm_f16_multi<<<dim3(D_ / 128, M_TOT / 128, 3), 256, GSMEM>>>(qa, ka, va);

    flash_hmma_kernel<<<dim3(L_ / 64, H_, B_), 128>>>(
        Qhi, Qlo, Khi, Vhi, mask, Athi, Atlo);

    gemm_f16_multi<<<dim3(D_ / 128, M_TOT / 128, 1), 256, GSMEM>>>(oa, oa, oa);
}

// round 10
// speedup vs baseline: 3.6598x; 1.0142x over previous
#include <cuda_runtime.h>
#include <cuda_fp16.h>
#include <cstdint>

#define B_   4
#define L_   1024
#define D_   1024
#define H_   16
#define HD_  64
#define M_TOT (B_ * L_)   // 4096

// Scratch (static device globals — allocation-guard safe)
__device__ __half g_Iqh[M_TOT * D_], g_Iql[M_TOT * D_];   // input splits
__device__ __half g_Ikh[M_TOT * D_], g_Ikl[M_TOT * D_];
__device__ __half g_Ivh[M_TOT * D_], g_Ivl[M_TOT * D_];
__device__ __half g_Wq16[D_ * D_], g_Wk16[D_ * D_], g_Wv16[D_ * D_], g_Wo16[D_ * D_];
__device__ __half g_Qhi[M_TOT * D_], g_Qlo[M_TOT * D_];   // projected
__device__ __half g_Khi[M_TOT * D_], g_Vhi[M_TOT * D_];
__device__ __half g_Athi[M_TOT * D_], g_Atlo[M_TOT * D_]; // attention out split

// ===========================================================================
// Helpers
// ===========================================================================
__device__ __forceinline__ uint32_t smem_u32(const void* p) {
    uint32_t a;
    asm("{ .reg .u64 t; cvta.to.shared.u64 t, %1; cvt.u32.u64 %0, t; }" : "=r"(a) : "l"(p));
    return a;
}
__device__ __forceinline__ void ldsm_x4(uint32_t& r0, uint32_t& r1, uint32_t& r2, uint32_t& r3, uint32_t a) {
    asm volatile("ldmatrix.sync.aligned.m8n8.x4.shared.b16 {%0,%1,%2,%3}, [%4];"
                 : "=r"(r0), "=r"(r1), "=r"(r2), "=r"(r3) : "r"(a));
}
__device__ __forceinline__ void ldsm_x2(uint32_t& r0, uint32_t& r1, uint32_t a) {
    asm volatile("ldmatrix.sync.aligned.m8n8.x2.shared.b16 {%0,%1}, [%2];"
                 : "=r"(r0), "=r"(r1) : "r"(a));
}
__device__ __forceinline__ void ldsm_x2t(uint32_t& r0, uint32_t& r1, uint32_t a) {
    asm volatile("ldmatrix.sync.aligned.m8n8.x2.trans.shared.b16 {%0,%1}, [%2];"
                 : "=r"(r0), "=r"(r1) : "r"(a));
}
__device__ __forceinline__ void mma_f16(float* c,
    uint32_t a0, uint32_t a1, uint32_t a2, uint32_t a3, uint32_t b0, uint32_t b1) {
    asm volatile("mma.sync.aligned.m16n8k16.row.col.f32.f16.f16.f32 "
                 "{%0,%1,%2,%3}, {%4,%5,%6,%7}, {%8,%9}, {%0,%1,%2,%3};"
                 : "+f"(c[0]), "+f"(c[1]), "+f"(c[2]), "+f"(c[3])
                 : "r"(a0), "r"(a1), "r"(a2), "r"(a3), "r"(b0), "r"(b1));
}
__device__ __forceinline__ uint32_t pack_h(__half lo, __half hi) {
    return ((uint32_t)__half_as_ushort(hi) << 16) | __half_as_ushort(lo);
}
__device__ __forceinline__ void split2h(float x, __half& h, __half& l) {
    h = __float2half_rn(x);
    l = __float2half_rn(x - __half2float(h));
}
__device__ __forceinline__ void cp16(uint32_t dst, const void* src) {
    asm volatile("cp.async.cg.shared.global [%0], [%1], 16;" :: "r"(dst), "l"(src));
}
__device__ __forceinline__ void cp_commit() { asm volatile("cp.async.commit_group;"); }
template<int N> __device__ __forceinline__ void cp_wait() {
    asm volatile("cp.async.wait_group %0;" :: "n"(N));
}

// ===========================================================================
// Prep: split inputs to hi/lo fp16; round weights to fp16.  grid (512,1,7)
// ===========================================================================
__global__ __launch_bounds__(256) void prep_kernel(
    const float* __restrict__ q, const float* __restrict__ k, const float* __restrict__ v,
    const float* __restrict__ wq, const float* __restrict__ wk,
    const float* __restrict__ wv, const float* __restrict__ wo,
    __half* qh, __half* ql, __half* kh, __half* kl, __half* vh, __half* vl,
    __half* wqh, __half* wkh, __half* wvh, __half* woh)
{
    const int z = blockIdx.z;
    const int base = blockIdx.x * 256 + threadIdx.x;
    if (z < 3) {
        const float* src = (z == 0) ? q : (z == 1) ? k : v;
        __half* dh = (z == 0) ? qh : (z == 1) ? kh : vh;
        __half* dl = (z == 0) ? ql : (z == 1) ? kl : vl;
        #pragma unroll
        for (int i = 0; i < 8; i++) {
            int e4 = base + i * 131072;
            float4 x = reinterpret_cast<const float4*>(src)[e4];
            __half h0, h1, h2, h3, l0, l1, l2, l3;
            split2h(x.x, h0, l0); split2h(x.y, h1, l1);
            split2h(x.z, h2, l2); split2h(x.w, h3, l3);
            uint2 hv = { pack_h(h0, h1), pack_h(h2, h3) };
            uint2 lv = { pack_h(l0, l1), pack_h(l2, l3) };
            *reinterpret_cast<uint2*>(dh + (size_t)e4 * 4) = hv;
            *reinterpret_cast<uint2*>(dl + (size_t)e4 * 4) = lv;
        }
    } else {
        const float* src = (z == 3) ? wq : (z == 4) ? wk : (z == 5) ? wv : wo;
        __half* dst = (z == 3) ? wqh : (z == 4) ? wkh : (z == 5) ? wvh : woh;
        #pragma unroll
        for (int i = 0; i < 2; i++) {
            int e4 = base + i * 131072;
            float4 x = reinterpret_cast<const float4*>(src)[e4];
            uint2 wv2 = { pack_h(__float2half_rn(x.x), __float2half_rn(x.y)),
                          pack_h(__float2half_rn(x.z), __float2half_rn(x.w)) };
            *reinterpret_cast<uint2*>(dst + (size_t)e4 * 4) = wv2;
        }
    }
}

// ===========================================================================
// Pure-fp16 HMMA GEMM, cp.async double-buffered (unchanged from R9).
// ===========================================================================
#define BKC   32
#define NCH   (D_ / BKC)   // 32
#define SST   40
#define ARR_H (128 * SST)
#define STG_H (3 * ARR_H)
#define GSMEM (2 * STG_H * 2)          // 61440 bytes

struct GemmArgs {
    const __half* Ah;
    const __half* Al;
    const __half* Wh;
    const float*  bias;
    float*  C;
    __half* Chi;
    __half* Clo;
};

__device__ __forceinline__ void issue_chunk(
    const GemmArgs& g, int m0, int n0, int k0, int t, uint32_t stage_b)
{
    #pragma unroll
    for (int i = 0; i < 2; i++) {
        int s  = t + (i << 8);
        int r  = s >> 2;
        int c8 = (s & 3) << 3;
        uint32_t d = stage_b + (uint32_t)(r * SST + c8) * 2;
        size_t goff = (size_t)(m0 + r) * D_ + k0 + c8;
        cp16(d,                 g.Ah + goff);
        cp16(d + ARR_H * 2,     g.Al + goff);
        cp16(d + 2 * ARR_H * 2, g.Wh + (size_t)(n0 + r) * D_ + k0 + c8);
    }
}

__global__ __launch_bounds__(256, 2) void gemm_f16_multi(
    GemmArgs ga0, GemmArgs ga1, GemmArgs ga2)
{
    extern __shared__ __half dsm[];
    const GemmArgs g = (blockIdx.z == 0) ? ga0 : ((blockIdx.z == 1) ? ga1 : ga2);

    const int t    = threadIdx.x;
    const int lane = t & 31;
    const int warp = t >> 5;
    const int wm   = warp >> 2;
    const int wn   = warp & 3;
    const int m0   = blockIdx.y * 128;
    const int n0   = blockIdx.x * 128;
    const uint32_t sb = smem_u32(dsm);

    float acc[4][4][4];
    #pragma unroll
    for (int i = 0; i < 4; i++)
        #pragma unroll
        for (int j = 0; j < 4; j++)
            #pragma unroll
            for (int r = 0; r < 4; r++) acc[i][j][r] = 0.0f;

    issue_chunk(g, m0, n0, 0, t, sb);
    cp_commit();
    issue_chunk(g, m0, n0, BKC, t, sb + STG_H * 2);
    cp_commit();

    for (int ck = 0; ck < NCH; ck++) {
        const int st = ck & 1;
        const __half* cah = dsm + st * STG_H;
        const __half* cal = cah + ARR_H;
        const __half* cbh = cah + 2 * ARR_H;

        if (ck + 1 < NCH) cp_wait<1>(); else cp_wait<0>();
        __syncthreads();

        #pragma unroll
        for (int ks = 0; ks < 2; ks++) {
            const int k0 = ks * 16;
            uint32_t bh[4][2];
            #pragma unroll
            for (int j = 0; j < 4; j++) {
                int row = wn * 32 + j * 8 + (lane & 7);
                int col = k0 + (((lane >> 3) & 1) << 3);
                ldsm_x2(bh[j][0], bh[j][1], smem_u32(cbh + row * SST + col));
            }
            #pragma unroll
            for (int i = 0; i < 4; i++) {
                int row = wm * 64 + i * 16 + (lane & 15);
                int col = k0 + ((lane >> 4) << 3);
                uint32_t ah0, ah1, ah2, ah3, al0, al1, al2, al3;
                ldsm_x4(ah0, ah1, ah2, ah3, smem_u32(cah + row * SST + col));
                ldsm_x4(al0, al1, al2, al3, smem_u32(cal + row * SST + col));
                #pragma unroll
                for (int j = 0; j < 4; j++) {
                    mma_f16(acc[i][j], ah0, ah1, ah2, ah3, bh[j][0], bh[j][1]);
                    mma_f16(acc[i][j], al0, al1, al2, al3, bh[j][0], bh[j][1]);
                }
            }
        }
        __syncthreads();

        if (ck + 2 < NCH) {
            issue_chunk(g, m0, n0, (ck + 2) * BKC, t, sb + st * STG_H * 2);
            cp_commit();
        }
    }

    const int lr = lane >> 2;
    const int lc = (lane & 3) << 1;
    #pragma unroll
    for (int i = 0; i < 4; i++) {
        #pragma unroll
        for (int j = 0; j < 4; j++) {
            int row = m0 + wm * 64 + i * 16 + lr;
            int col = n0 + wn * 32 + j * 8 + lc;
            float2 bz = *reinterpret_cast<const float2*>(g.bias + col);
            float v0 = acc[i][j][0] + bz.x, v1 = acc[i][j][1] + bz.y;
            float v2 = acc[i][j][2] + bz.x, v3 = acc[i][j][3] + bz.y;
            if (g.Chi) {
                if (g.Clo) {
                    __half h0, h1, h2, h3, l0, l1, l2, l3;
                    split2h(v0, h0, l0); split2h(v1, h1, l1);
                    split2h(v2, h2, l2); split2h(v3, h3, l3);
                    *reinterpret_cast<uint32_t*>(g.Chi + (size_t)row * D_ + col)       = pack_h(h0, h1);
                    *reinterpret_cast<uint32_t*>(g.Clo + (size_t)row * D_ + col)       = pack_h(l0, l1);
                    *reinterpret_cast<uint32_t*>(g.Chi + (size_t)(row + 8) * D_ + col) = pack_h(h2, h3);
                    *reinterpret_cast<uint32_t*>(g.Clo + (size_t)(row + 8) * D_ + col) = pack_h(l2, l3);
                } else {
                    *reinterpret_cast<uint32_t*>(g.Chi + (size_t)row * D_ + col) =
                        pack_h(__float2half_rn(v0), __float2half_rn(v1));
                    *reinterpret_cast<uint32_t*>(g.Chi + (size_t)(row + 8) * D_ + col) =
                        pack_h(__float2half_rn(v2), __float2half_rn(v3));
                }
            } else {
                float2 o0 = { v0, v1 }, o1 = { v2, v3 };
                *reinterpret_cast<float2*>(g.C + (size_t)row * D_ + col) = o0;
                *reinterpret_cast<float2*>(g.C + (size_t)(row + 8) * D_ + col) = o1;
            }
        }
    }
}

// ===========================================================================
// HMMA flash attention, cp.async double-buffered K/V, 128 q-rows / 8 warps.
//   S = Qhi*K + Qlo*K ; P split hi/lo ; O += Phi*V + Plo*V
// ===========================================================================
#define FST 72

__global__ __launch_bounds__(256) void flash_hmma_kernel(
    const __half* __restrict__ Qhi, const __half* __restrict__ Qlo,
    const __half* __restrict__ Khi, const __half* __restrict__ Vhi,
    const int* __restrict__ mask,
    __half* __restrict__ Oh, __half* __restrict__ Ol)
{
    __shared__ __align__(16) __half KH[2][64][FST];
    __shared__ __align__(16) __half VH[2][64][FST];
    __shared__ int MI[2][64];

    const int t    = threadIdx.x;
    const int lane = t & 31;
    const int warp = t >> 5;
    const int qt   = blockIdx.x;
    const int h    = blockIdx.y;
    const int b    = blockIdx.z;
    const int grow0 = b * L_ + qt * 128;
    const int ghc   = h * HD_;
    const float scale = 0.125f;

    // ---- stage Q tile (128 rows): hi -> KH0|VH0, lo -> KH1|VH1 ----
    #pragma unroll
    for (int i = 0; i < 4; i++) {
        int v = t + i * 256;       // 0..1023
        int r = v >> 3;            // 0..127
        int c = (v & 7) << 3;
        __half* dh = (r < 64) ? &KH[0][r][c] : &VH[0][r - 64][c];
        __half* dl = (r < 64) ? &KH[1][r][c] : &VH[1][r - 64][c];
        *reinterpret_cast<uint4*>(dh) =
            *reinterpret_cast<const uint4*>(Qhi + (size_t)(grow0 + r) * D_ + ghc + c);
        *reinterpret_cast<uint4*>(dl) =
            *reinterpret_cast<const uint4*>(Qlo + (size_t)(grow0 + r) * D_ + ghc + c);
    }
    __syncthreads();

    uint32_t qh[4][4], ql[4][4];
    {
        int ar = warp * 16 + (lane & 15);       // 0..127, same array per warp
        int ac = (lane >> 4) << 3;
        const __half* sh = (ar < 64) ? &KH[0][ar][0] : &VH[0][ar - 64][0];
        const __half* sl = (ar < 64) ? &KH[1][ar][0] : &VH[1][ar - 64][0];
        #pragma unroll
        for (int kc = 0; kc < 4; kc++) {
            ldsm_x4(qh[kc][0], qh[kc][1], qh[kc][2], qh[kc][3], smem_u32(sh + kc * 16 + ac));
            ldsm_x4(ql[kc][0], ql[kc][1], ql[kc][2], ql[kc][3], smem_u32(sl + kc * 16 + ac));
        }
    }
    __syncthreads();   // Q fragments read; smem stages free for K/V

    float O[8][4];
    #pragma unroll
    for (int j = 0; j < 8; j++)
        #pragma unroll
        for (int r = 0; r < 4; r++) O[j][r] = 0.0f;
    float m0 = -1e30f, m1 = -1e30f, l0 = 0.0f, l1 = 0.0f;

    // ---- K/V/mask tile issue via cp.async ----
    auto issue_kv = [&](int tile, int st) {
        const int krow0 = b * L_ + tile * 64;
        #pragma unroll
        for (int i = 0; i < 2; i++) {
            int s = t + i * 256;       // 0..511
            int r = s >> 3;            // 0..63
            int c = (s & 7) << 3;
            size_t gb = (size_t)(krow0 + r) * D_ + ghc + c;
            cp16(smem_u32(&KH[st][r][c]), Khi + gb);
            cp16(smem_u32(&VH[st][r][c]), Vhi + gb);
        }
        if (t < 16) cp16(smem_u32(&MI[st][t * 4]), mask + b * L_ + tile * 64 + t * 4);
        cp_commit();
    };

    issue_kv(0, 0);
    issue_kv(1, 1);

    for (int kt = 0; kt < 16; kt++) {
        const int st = kt & 1;
        if (kt + 1 < 16) cp_wait<1>(); else cp_wait<0>();
        __syncthreads();

        // ---- S = Q K^T (2-term) ----
        float S[8][4];
        #pragma unroll
        for (int j = 0; j < 8; j++) {
            S[j][0] = S[j][1] = S[j][2] = S[j][3] = 0.0f;
            int brow = j * 8 + (lane & 7);
            #pragma unroll
            for (int kc = 0; kc < 4; kc++) {
                int bcol = kc * 16 + (((lane >> 3) & 1) << 3);
                uint32_t bh0, bh1;
                ldsm_x2(bh0, bh1, smem_u32(&KH[st][brow][bcol]));
                mma_f16(S[j], qh[kc][0], qh[kc][1], qh[kc][2], qh[kc][3], bh0, bh1);
                mma_f16(S[j], ql[kc][0], ql[kc][1], ql[kc][2], ql[kc][3], bh0, bh1);
            }
        }

        // ---- softmax ----
        float rmax0 = -3.0e38f, rmax1 = -3.0e38f;
        #pragma unroll
        for (int j = 0; j < 8; j++) {
            int cidx = j * 8 + ((lane & 3) << 1);
            float ma = MI[st][cidx]     ? -1e30f : 0.0f;
            float mb = MI[st][cidx + 1] ? -1e30f : 0.0f;
            S[j][0] = S[j][0] * scale + ma;
            S[j][1] = S[j][1] * scale + mb;
            S[j][2] = S[j][2] * scale + ma;
            S[j][3] = S[j][3] * scale + mb;
            rmax0 = fmaxf(rmax0, fmaxf(S[j][0], S[j][1]));
            rmax1 = fmaxf(rmax1, fmaxf(S[j][2], S[j][3]));
        }
        rmax0 = fmaxf(rmax0, __shfl_xor_sync(0xffffffffu, rmax0, 1));
        rmax0 = fmaxf(rmax0, __shfl_xor_sync(0xffffffffu, rmax0, 2));
        rmax1 = fmaxf(rmax1, __shfl_xor_sync(0xffffffffu, rmax1, 1));
        rmax1 = fmaxf(rmax1, __shfl_xor_sync(0xffffffffu, rmax1, 2));

        float mn0 = fmaxf(m0, rmax0), mn1 = fmaxf(m1, rmax1);
        float a0 = __expf(m0 - mn0), a1 = __expf(m1 - mn1);
        m0 = mn0; m1 = mn1;

        float sum0 = 0.0f, sum1 = 0.0f;
        #pragma unroll
        for (int j = 0; j < 8; j++) {
            S[j][0] = __expf(S[j][0] - mn0); sum0 += S[j][0];
            S[j][1] = __expf(S[j][1] - mn0); sum0 += S[j][1];
            S[j][2] = __expf(S[j][2] - mn1); sum1 += S[j][2];
            S[j][3] = __expf(S[j][3] - mn1); sum1 += S[j][3];
        }
        sum0 += __shfl_xor_sync(0xffffffffu, sum0, 1);
        sum0 += __shfl_xor_sync(0xffffffffu, sum0, 2);
        sum1 += __shfl_xor_sync(0xffffffffu, sum1, 1);
        sum1 += __shfl_xor_sync(0xffffffffu, sum1, 2);
        l0 = l0 * a0 + sum0;
        l1 = l1 * a1 + sum1;

        #pragma unroll
        for (int j = 0; j < 8; j++) {
            O[j][0] *= a0; O[j][1] *= a0; O[j][2] *= a1; O[j][3] *= a1;
        }

        // ---- split P into hi/lo A-fragments ----
        uint32_t ph[4][4], pl[4][4];
        #pragma unroll
        for (int kc = 0; kc < 4; kc++) {
            const float* x = S[2 * kc];
            const float* y = S[2 * kc + 1];
            __half h0, h1, h2, h3, g0, g1, g2, g3;
            __half e0, e1, e2, e3, f0, f1, f2, f3;
            split2h(x[0], h0, e0); split2h(x[1], h1, e1);
            split2h(x[2], h2, e2); split2h(x[3], h3, e3);
            split2h(y[0], g0, f0); split2h(y[1], g1, f1);
            split2h(y[2], g2, f2); split2h(y[3], g3, f3);
            ph[kc][0] = pack_h(h0, h1); ph[kc][1] = pack_h(h2, h3);
            ph[kc][2] = pack_h(g0, g1); ph[kc][3] = pack_h(g2, g3);
            pl[kc][0] = pack_h(e0, e1); pl[kc][1] = pack_h(e2, e3);
            pl[kc][2] = pack_h(f0, f1); pl[kc][3] = pack_h(f2, f3);
        }

        // ---- O += P V (2-term); V via ldmatrix.trans ----
        #pragma unroll
        for (int jn = 0; jn < 8; jn++) {
            #pragma unroll
            for (int kc = 0; kc < 4; kc++) {
                int vrow = kc * 16 + (lane & 15);
                uint32_t vh0, vh1;
                ldsm_x2t(vh0, vh1, smem_u32(&VH[st][vrow][jn * 8]));
                mma_f16(O[jn], ph[kc][0], ph[kc][1], ph[kc][2], ph[kc][3], vh0, vh1);
                mma_f16(O[jn], pl[kc][0], pl[kc][1], pl[kc][2], pl[kc][3], vh0, vh1);
            }
        }
        __syncthreads();

        if (kt + 2 < 16) issue_kv(kt + 2, st);
    }

    // ---- normalize + write hi/lo fp16 ----
    float inv0 = l0 > 0.0f ? 1.0f / l0 : 0.0f;
    float inv1 = l1 > 0.0f ? 1.0f / l1 : 0.0f;
    int row0 = grow0 + warp * 16 + (lane >> 2);
    int col  = ghc + ((lane & 3) << 1);
    #pragma unroll
    for (int jn = 0; jn < 8; jn++) {
        float x0 = O[jn][0] * inv0, x1 = O[jn][1] * inv0;
        float x2 = O[jn][2] * inv1, x3 = O[jn][3] * inv1;
        __half h0, h1, h2, h3, e0, e1, e2, e3;
        split2h(x0, h0, e0); split2h(x1, h1, e1);
        split2h(x2, h2, e2); split2h(x3, h3, e3);
        *reinterpret_cast<uint32_t*>(Oh + (size_t)row0 * D_ + col + jn * 8)       = pack_h(h0, h1);
        *reinterpret_cast<uint32_t*>(Ol + (size_t)row0 * D_ + col + jn * 8)       = pack_h(e0, e1);
        *reinterpret_cast<uint32_t*>(Oh + (size_t)(row0 + 8) * D_ + col + jn * 8) = pack_h(h2, h3);
        *reinterpret_cast<uint32_t*>(Ol + (size_t)(row0 + 8) * D_ + col + jn * 8) = pack_h(e2, e3);
    }
}

// ---------------------------------------------------------------------------
// Launch
// ---------------------------------------------------------------------------
extern "C" void kernel_launch(void* const* d_in, const int* in_sizes, int n_in,
                              void* d_out, int out_size)
{
    const float* query = (const float*)d_in[0];
    const float* key   = (const float*)d_in[1];
    const float* value = (const float*)d_in[2];
    const int*   mask  = (const int*)d_in[3];
    const float* Wq = (const float*)d_in[4];
    const float* bq = (const float*)d_in[5];
    const float* Wk = (const float*)d_in[6];
    const float* bk = (const float*)d_in[7];
    const float* Wv = (const float*)d_in[8];
    const float* bv = (const float*)d_in[9];
    const float* Wo = (const float*)d_in[10];
    const float* bo = (const float*)d_in[11];
    float* out = (float*)d_out;

    void *p[16];
    cudaGetSymbolAddress(&p[0],  g_Iqh);  cudaGetSymbolAddress(&p[1],  g_Iql);
    cudaGetSymbolAddress(&p[2],  g_Ikh);  cudaGetSymbolAddress(&p[3],  g_Ikl);
    cudaGetSymbolAddress(&p[4],  g_Ivh);  cudaGetSymbolAddress(&p[5],  g_Ivl);
    cudaGetSymbolAddress(&p[6],  g_Wq16); cudaGetSymbolAddress(&p[7],  g_Wk16);
    cudaGetSymbolAddress(&p[8],  g_Wv16); cudaGetSymbolAddress(&p[9],  g_Wo16);
    cudaGetSymbolAddress(&p[10], g_Qhi);  cudaGetSymbolAddress(&p[11], g_Qlo);
    cudaGetSymbolAddress(&p[12], g_Khi);  cudaGetSymbolAddress(&p[13], g_Vhi);
    cudaGetSymbolAddress(&p[14], g_Athi); cudaGetSymbolAddress(&p[15], g_Atlo);
    __half* Iqh = (__half*)p[0];  __half* Iql = (__half*)p[1];
    __half* Ikh = (__half*)p[2];  __half* Ikl = (__half*)p[3];
    __half* Ivh = (__half*)p[4];  __half* Ivl = (__half*)p[5];
    __half* Wq16 = (__half*)p[6]; __half* Wk16 = (__half*)p[7];
    __half* Wv16 = (__half*)p[8]; __half* Wo16 = (__half*)p[9];
    __half* Qhi = (__half*)p[10]; __half* Qlo = (__half*)p[11];
    __half* Khi = (__half*)p[12]; __half* Vhi = (__half*)p[13];
    __half* Athi = (__half*)p[14]; __half* Atlo = (__half*)p[15];

    cudaFuncSetAttribute(gemm_f16_multi,
                         cudaFuncAttributeMaxDynamicSharedMemorySize, GSMEM);

    prep_kernel<<<dim3(512, 1, 7), 256>>>(
        query, key, value, Wq, Wk, Wv, Wo,
        Iqh, Iql, Ikh, Ikl, Ivh, Ivl, Wq16, Wk16, Wv16, Wo16);

    GemmArgs qa = { Iqh, Iql, Wq16, bq, nullptr, Qhi, Qlo };
    GemmArgs ka = { Ikh, Ikl, Wk16, bk, nullptr, Khi, nullptr };
    GemmArgs va = { Ivh, Ivl, Wv16, bv, nullptr, Vhi, nullptr };
    GemmArgs oa = { Athi, Atlo, Wo16, bo, out, nullptr, nullptr };

    gemm_f16_multi<<<dim3(D_ / 128, M_TOT / 128, 3), 256, GSMEM>>>(qa, ka, va);

    flash_hmma_kernel<<<dim3(L_ / 128, H_, B_), 256>>>(
        Qhi, Qlo, Khi, Vhi, mask, Athi, Atlo);

    gemm_f16_multi<<<dim3(D_ / 128, M_TOT / 128, 1), 256, GSMEM>>>(oa, oa, oa);
}

// round 12
// speedup vs baseline: 3.9511x; 1.0796x over previous
#include <cuda_runtime.h>
#include <cuda_fp16.h>
#include <cstdint>

#define B_   4
#define L_   1024
#define D_   1024
#define H_   16
#define HD_  64
#define M_TOT (B_ * L_)   // 4096

// Scratch (static device globals — allocation-guard safe)
__device__ __half g_Iqh[M_TOT * D_], g_Iql[M_TOT * D_];   // input splits
__device__ __half g_Ikh[M_TOT * D_], g_Ikl[M_TOT * D_];
__device__ __half g_Ivh[M_TOT * D_], g_Ivl[M_TOT * D_];
__device__ __half g_Wq16[D_ * D_], g_Wk16[D_ * D_], g_Wv16[D_ * D_], g_Wo16[D_ * D_];
__device__ __half g_Qhi[M_TOT * D_], g_Qlo[M_TOT * D_];   // projected (pre-scaled by 1/8)
__device__ __half g_Khi[M_TOT * D_], g_Vhi[M_TOT * D_];
__device__ __half g_Athi[M_TOT * D_];                     // attention out (single fp16)

// ===========================================================================
// Helpers
// ===========================================================================
__device__ __forceinline__ uint32_t smem_u32(const void* p) {
    uint32_t a;
    asm("{ .reg .u64 t; cvta.to.shared.u64 t, %1; cvt.u32.u64 %0, t; }" : "=r"(a) : "l"(p));
    return a;
}
__device__ __forceinline__ void ldsm_x4(uint32_t& r0, uint32_t& r1, uint32_t& r2, uint32_t& r3, uint32_t a) {
    asm volatile("ldmatrix.sync.aligned.m8n8.x4.shared.b16 {%0,%1,%2,%3}, [%4];"
                 : "=r"(r0), "=r"(r1), "=r"(r2), "=r"(r3) : "r"(a));
}
__device__ __forceinline__ void ldsm_x2(uint32_t& r0, uint32_t& r1, uint32_t a) {
    asm volatile("ldmatrix.sync.aligned.m8n8.x2.shared.b16 {%0,%1}, [%2];"
                 : "=r"(r0), "=r"(r1) : "r"(a));
}
__device__ __forceinline__ void ldsm_x2t(uint32_t& r0, uint32_t& r1, uint32_t a) {
    asm volatile("ldmatrix.sync.aligned.m8n8.x2.trans.shared.b16 {%0,%1}, [%2];"
                 : "=r"(r0), "=r"(r1) : "r"(a));
}
__device__ __forceinline__ void mma_f16(float* c,
    uint32_t a0, uint32_t a1, uint32_t a2, uint32_t a3, uint32_t b0, uint32_t b1) {
    asm volatile("mma.sync.aligned.m16n8k16.row.col.f32.f16.f16.f32 "
                 "{%0,%1,%2,%3}, {%4,%5,%6,%7}, {%8,%9}, {%0,%1,%2,%3};"
                 : "+f"(c[0]), "+f"(c[1]), "+f"(c[2]), "+f"(c[3])
                 : "r"(a0), "r"(a1), "r"(a2), "r"(a3), "r"(b0), "r"(b1));
}
__device__ __forceinline__ uint32_t pack_h(__half lo, __half hi) {
    return ((uint32_t)__half_as_ushort(hi) << 16) | __half_as_ushort(lo);
}
__device__ __forceinline__ void split2h(float x, __half& h, __half& l) {
    h = __float2half_rn(x);
    l = __float2half_rn(x - __half2float(h));
}
__device__ __forceinline__ void cp16(uint32_t dst, const void* src) {
    asm volatile("cp.async.cg.shared.global [%0], [%1], 16;" :: "r"(dst), "l"(src));
}
__device__ __forceinline__ void cp_commit() { asm volatile("cp.async.commit_group;"); }
template<int N> __device__ __forceinline__ void cp_wait() {
    asm volatile("cp.async.wait_group %0;" :: "n"(N));
}

// ===========================================================================
// Prep: split inputs to hi/lo fp16; round weights to fp16.  grid (512,1,7)
// ===========================================================================
__global__ __launch_bounds__(256) void prep_kernel(
    const float* __restrict__ q, const float* __restrict__ k, const float* __restrict__ v,
    const float* __restrict__ wq, const float* __restrict__ wk,
    const float* __restrict__ wv, const float* __restrict__ wo,
    __half* qh, __half* ql, __half* kh, __half* kl, __half* vh, __half* vl,
    __half* wqh, __half* wkh, __half* wvh, __half* woh)
{
    const int z = blockIdx.z;
    const int base = blockIdx.x * 256 + threadIdx.x;
    if (z < 3) {
        const float* src = (z == 0) ? q : (z == 1) ? k : v;
        __half* dh = (z == 0) ? qh : (z == 1) ? kh : vh;
        __half* dl = (z == 0) ? ql : (z == 1) ? kl : vl;
        #pragma unroll
        for (int i = 0; i < 8; i++) {
            int e4 = base + i * 131072;
            float4 x = reinterpret_cast<const float4*>(src)[e4];
            __half h0, h1, h2, h3, l0, l1, l2, l3;
            split2h(x.x, h0, l0); split2h(x.y, h1, l1);
            split2h(x.z, h2, l2); split2h(x.w, h3, l3);
            uint2 hv = { pack_h(h0, h1), pack_h(h2, h3) };
            uint2 lv = { pack_h(l0, l1), pack_h(l2, l3) };
            *reinterpret_cast<uint2*>(dh + (size_t)e4 * 4) = hv;
            *reinterpret_cast<uint2*>(dl + (size_t)e4 * 4) = lv;
        }
    } else {
        const float* src = (z == 3) ? wq : (z == 4) ? wk : (z == 5) ? wv : wo;
        __half* dst = (z == 3) ? wqh : (z == 4) ? wkh : (z == 5) ? wvh : woh;
        #pragma unroll
        for (int i = 0; i < 2; i++) {
            int e4 = base + i * 131072;
            float4 x = reinterpret_cast<const float4*>(src)[e4];
            uint2 wv2 = { pack_h(__float2half_rn(x.x), __float2half_rn(x.y)),
                          pack_h(__float2half_rn(x.z), __float2half_rn(x.w)) };
            *reinterpret_cast<uint2*>(dst + (size_t)e4 * 4) = wv2;
        }
    }
}

// ===========================================================================
// fp16 HMMA GEMM, cp.async double-buffered. A-side 1- or 2-term (two_term flag).
//   C = (Ah [+ Al]) @ Wh^T + bias, then * oscale.
// ===========================================================================
#define BKC   32
#define NCH   (D_ / BKC)   // 32
#define SST   40
#define ARR_H (128 * SST)
#define STG_H (3 * ARR_H)
#define GSMEM (2 * STG_H * 2)          // 61440 bytes

struct GemmArgs {
    const __half* Ah;
    const __half* Al;
    const __half* Wh;
    const float*  bias;
    float*  C;
    __half* Chi;
    __half* Clo;
    int     two_term;   // A-side lo term present
    float   oscale;     // output scale (applied after bias)
};

__device__ __forceinline__ void issue_chunk(
    const GemmArgs& g, int m0, int n0, int k0, int t, uint32_t stage_b)
{
    #pragma unroll
    for (int i = 0; i < 2; i++) {
        int s  = t + (i << 8);
        int r  = s >> 2;
        int c8 = (s & 3) << 3;
        uint32_t d = stage_b + (uint32_t)(r * SST + c8) * 2;
        size_t goff = (size_t)(m0 + r) * D_ + k0 + c8;
        cp16(d, g.Ah + goff);
        if (g.two_term) cp16(d + ARR_H * 2, g.Al + goff);
        cp16(d + 2 * ARR_H * 2, g.Wh + (size_t)(n0 + r) * D_ + k0 + c8);
    }
}

__global__ __launch_bounds__(256, 2) void gemm_f16_multi(
    GemmArgs ga0, GemmArgs ga1, GemmArgs ga2)
{
    extern __shared__ __half dsm[];
    const GemmArgs g = (blockIdx.z == 0) ? ga0 : ((blockIdx.z == 1) ? ga1 : ga2);

    const int t    = threadIdx.x;
    const int lane = t & 31;
    const int warp = t >> 5;
    const int wm   = warp >> 2;
    const int wn   = warp & 3;
    const int m0   = blockIdx.y * 128;
    const int n0   = blockIdx.x * 128;
    const uint32_t sb = smem_u32(dsm);

    float acc[4][4][4];
    #pragma unroll
    for (int i = 0; i < 4; i++)
        #pragma unroll
        for (int j = 0; j < 4; j++)
            #pragma unroll
            for (int r = 0; r < 4; r++) acc[i][j][r] = 0.0f;

    issue_chunk(g, m0, n0, 0, t, sb);
    cp_commit();
    issue_chunk(g, m0, n0, BKC, t, sb + STG_H * 2);
    cp_commit();

    for (int ck = 0; ck < NCH; ck++) {
        const int st = ck & 1;
        const __half* cah = dsm + st * STG_H;
        const __half* cal = cah + ARR_H;
        const __half* cbh = cah + 2 * ARR_H;

        if (ck + 1 < NCH) cp_wait<1>(); else cp_wait<0>();
        __syncthreads();

        #pragma unroll
        for (int ks = 0; ks < 2; ks++) {
            const int k0 = ks * 16;
            uint32_t bh[4][2];
            #pragma unroll
            for (int j = 0; j < 4; j++) {
                int row = wn * 32 + j * 8 + (lane & 7);
                int col = k0 + (((lane >> 3) & 1) << 3);
                ldsm_x2(bh[j][0], bh[j][1], smem_u32(cbh + row * SST + col));
            }
            #pragma unroll
            for (int i = 0; i < 4; i++) {
                int row = wm * 64 + i * 16 + (lane & 15);
                int col = k0 + ((lane >> 4) << 3);
                uint32_t ah0, ah1, ah2, ah3;
                ldsm_x4(ah0, ah1, ah2, ah3, smem_u32(cah + row * SST + col));
                #pragma unroll
                for (int j = 0; j < 4; j++)
                    mma_f16(acc[i][j], ah0, ah1, ah2, ah3, bh[j][0], bh[j][1]);
                if (g.two_term) {
                    uint32_t al0, al1, al2, al3;
                    ldsm_x4(al0, al1, al2, al3, smem_u32(cal + row * SST + col));
                    #pragma unroll
                    for (int j = 0; j < 4; j++)
                        mma_f16(acc[i][j], al0, al1, al2, al3, bh[j][0], bh[j][1]);
                }
            }
        }
        __syncthreads();

        if (ck + 2 < NCH) {
            issue_chunk(g, m0, n0, (ck + 2) * BKC, t, sb + st * STG_H * 2);
            cp_commit();
        }
    }

    const int lr = lane >> 2;
    const int lc = (lane & 3) << 1;
    #pragma unroll
    for (int i = 0; i < 4; i++) {
        #pragma unroll
        for (int j = 0; j < 4; j++) {
            int row = m0 + wm * 64 + i * 16 + lr;
            int col = n0 + wn * 32 + j * 8 + lc;
            float2 bz = *reinterpret_cast<const float2*>(g.bias + col);
            float v0 = (acc[i][j][0] + bz.x) * g.oscale;
            float v1 = (acc[i][j][1] + bz.y) * g.oscale;
            float v2 = (acc[i][j][2] + bz.x) * g.oscale;
            float v3 = (acc[i][j][3] + bz.y) * g.oscale;
            if (g.Chi) {
                if (g.Clo) {
                    __half h0, h1, h2, h3, l0, l1, l2, l3;
                    split2h(v0, h0, l0); split2h(v1, h1, l1);
                    split2h(v2, h2, l2); split2h(v3, h3, l3);
                    *reinterpret_cast<uint32_t*>(g.Chi + (size_t)row * D_ + col)       = pack_h(h0, h1);
                    *reinterpret_cast<uint32_t*>(g.Clo + (size_t)row * D_ + col)       = pack_h(l0, l1);
                    *reinterpret_cast<uint32_t*>(g.Chi + (size_t)(row + 8) * D_ + col) = pack_h(h2, h3);
                    *reinterpret_cast<uint32_t*>(g.Clo + (size_t)(row + 8) * D_ + col) = pack_h(l2, l3);
                } else {
                    *reinterpret_cast<uint32_t*>(g.Chi + (size_t)row * D_ + col) =
                        pack_h(__float2half_rn(v0), __float2half_rn(v1));
                    *reinterpret_cast<uint32_t*>(g.Chi + (size_t)(row + 8) * D_ + col) =
                        pack_h(__float2half_rn(v2), __float2half_rn(v3));
                }
            } else {
                float2 o0 = { v0, v1 }, o1 = { v2, v3 };
                *reinterpret_cast<float2*>(g.C + (size_t)row * D_ + col) = o0;
                *reinterpret_cast<float2*>(g.C + (size_t)(row + 8) * D_ + col) = o1;
            }
        }
    }
}

// ===========================================================================
// HMMA flash attention: Q 2-term (pre-scaled by 1/8), K/V/P/At single fp16.
//   S = Qhi*K + Qlo*K ; P = fp16(softmax) ; O += P*V ; At = fp16(O/l)
// ===========================================================================
#define FST 72

__global__ __launch_bounds__(256) void flash_hmma_kernel(
    const __half* __restrict__ Qhi, const __half* __restrict__ Qlo,
    const __half* __restrict__ Khi, const __half* __restrict__ Vhi,
    const int* __restrict__ mask,
    __half* __restrict__ Oh)
{
    __shared__ __align__(16) __half KH[2][64][FST];
    __shared__ __align__(16) __half VH[2][64][FST];
    __shared__ int MI[2][64];

    const int t    = threadIdx.x;
    const int lane = t & 31;
    const int warp = t >> 5;
    const int qt   = blockIdx.x;
    const int h    = blockIdx.y;
    const int b    = blockIdx.z;
    const int grow0 = b * L_ + qt * 128;
    const int ghc   = h * HD_;

    // ---- stage Q tile (128 rows): hi -> KH0|VH0, lo -> KH1|VH1 ----
    #pragma unroll
    for (int i = 0; i < 4; i++) {
        int v = t + i * 256;
        int r = v >> 3;
        int c = (v & 7) << 3;
        __half* dh = (r < 64) ? &KH[0][r][c] : &VH[0][r - 64][c];
        __half* dl = (r < 64) ? &KH[1][r][c] : &VH[1][r - 64][c];
        *reinterpret_cast<uint4*>(dh) =
            *reinterpret_cast<const uint4*>(Qhi + (size_t)(grow0 + r) * D_ + ghc + c);
        *reinterpret_cast<uint4*>(dl) =
            *reinterpret_cast<const uint4*>(Qlo + (size_t)(grow0 + r) * D_ + ghc + c);
    }
    __syncthreads();

    uint32_t qh[4][4], ql[4][4];
    {
        int ar = warp * 16 + (lane & 15);
        int ac = (lane >> 4) << 3;
        const __half* sh = (ar < 64) ? &KH[0][ar][0] : &VH[0][ar - 64][0];
        const __half* sl = (ar < 64) ? &KH[1][ar][0] : &VH[1][ar - 64][0];
        #pragma unroll
        for (int kc = 0; kc < 4; kc++) {
            ldsm_x4(qh[kc][0], qh[kc][1], qh[kc][2], qh[kc][3], smem_u32(sh + kc * 16 + ac));
            ldsm_x4(ql[kc][0], ql[kc][1], ql[kc][2], ql[kc][3], smem_u32(sl + kc * 16 + ac));
        }
    }
    __syncthreads();   // Q fragments read; smem stages free for K/V

    float O[8][4];
    #pragma unroll
    for (int j = 0; j < 8; j++)
        #pragma unroll
        for (int r = 0; r < 4; r++) O[j][r] = 0.0f;
    float m0 = -1e30f, m1 = -1e30f, l0 = 0.0f, l1 = 0.0f;

    auto issue_kv = [&](int tile, int st) {
        const int krow0 = b * L_ + tile * 64;
        #pragma unroll
        for (int i = 0; i < 2; i++) {
            int s = t + i * 256;
            int r = s >> 3;
            int c = (s & 7) << 3;
            size_t gb = (size_t)(krow0 + r) * D_ + ghc + c;
            cp16(smem_u32(&KH[st][r][c]), Khi + gb);
            cp16(smem_u32(&VH[st][r][c]), Vhi + gb);
        }
        if (t < 16) cp16(smem_u32(&MI[st][t * 4]), mask + b * L_ + tile * 64 + t * 4);
        cp_commit();
    };

    issue_kv(0, 0);
    issue_kv(1, 1);

    for (int kt = 0; kt < 16; kt++) {
        const int st = kt & 1;
        if (kt + 1 < 16) cp_wait<1>(); else cp_wait<0>();
        __syncthreads();

        // ---- S = Q K^T (Q pre-scaled; 2-term in Q) ----
        float S[8][4];
        #pragma unroll
        for (int j = 0; j < 8; j++) {
            S[j][0] = S[j][1] = S[j][2] = S[j][3] = 0.0f;
            int brow = j * 8 + (lane & 7);
            #pragma unroll
            for (int kc = 0; kc < 4; kc++) {
                int bcol = kc * 16 + (((lane >> 3) & 1) << 3);
                uint32_t bh0, bh1;
                ldsm_x2(bh0, bh1, smem_u32(&KH[st][brow][bcol]));
                mma_f16(S[j], qh[kc][0], qh[kc][1], qh[kc][2], qh[kc][3], bh0, bh1);
                mma_f16(S[j], ql[kc][0], ql[kc][1], ql[kc][2], ql[kc][3], bh0, bh1);
            }
        }

        // ---- softmax (scale already folded into Q) ----
        float rmax0 = -3.0e38f, rmax1 = -3.0e38f;
        #pragma unroll
        for (int j = 0; j < 8; j++) {
            int cidx = j * 8 + ((lane & 3) << 1);
            float ma = MI[st][cidx]     ? -1e30f : 0.0f;
            float mb = MI[st][cidx + 1] ? -1e30f : 0.0f;
            S[j][0] += ma; S[j][1] += mb; S[j][2] += ma; S[j][3] += mb;
            rmax0 = fmaxf(rmax0, fmaxf(S[j][0], S[j][1]));
            rmax1 = fmaxf(rmax1, fmaxf(S[j][2], S[j][3]));
        }
        rmax0 = fmaxf(rmax0, __shfl_xor_sync(0xffffffffu, rmax0, 1));
        rmax0 = fmaxf(rmax0, __shfl_xor_sync(0xffffffffu, rmax0, 2));
        rmax1 = fmaxf(rmax1, __shfl_xor_sync(0xffffffffu, rmax1, 1));
        rmax1 = fmaxf(rmax1, __shfl_xor_sync(0xffffffffu, rmax1, 2));

        float mn0 = fmaxf(m0, rmax0), mn1 = fmaxf(m1, rmax1);
        float a0 = __expf(m0 - mn0), a1 = __expf(m1 - mn1);
        m0 = mn0; m1 = mn1;

        float sum0 = 0.0f, sum1 = 0.0f;
        #pragma unroll
        for (int j = 0; j < 8; j++) {
            S[j][0] = __expf(S[j][0] - mn0); sum0 += S[j][0];
            S[j][1] = __expf(S[j][1] - mn0); sum0 += S[j][1];
            S[j][2] = __expf(S[j][2] - mn1); sum1 += S[j][2];
            S[j][3] = __expf(S[j][3] - mn1); sum1 += S[j][3];
        }
        sum0 += __shfl_xor_sync(0xffffffffu, sum0, 1);
        sum0 += __shfl_xor_sync(0xffffffffu, sum0, 2);
        sum1 += __shfl_xor_sync(0xffffffffu, sum1, 1);
        sum1 += __shfl_xor_sync(0xffffffffu, sum1, 2);
        l0 = l0 * a0 + sum0;
        l1 = l1 * a1 + sum1;

        #pragma unroll
        for (int j = 0; j < 8; j++) {
            O[j][0] *= a0; O[j][1] *= a0; O[j][2] *= a1; O[j][3] *= a1;
        }

        // ---- P -> single fp16 A-fragments ----
        uint32_t ph[4][4];
        #pragma unroll
        for (int kc = 0; kc < 4; kc++) {
            const float* x = S[2 * kc];
            const float* y = S[2 * kc + 1];
            ph[kc][0] = pack_h(__float2half_rn(x[0]), __float2half_rn(x[1]));
            ph[kc][1] = pack_h(__float2half_rn(x[2]), __float2half_rn(x[3]));
            ph[kc][2] = pack_h(__float2half_rn(y[0]), __float2half_rn(y[1]));
            ph[kc][3] = pack_h(__float2half_rn(y[2]), __float2half_rn(y[3]));
        }

        // ---- O += P V (single term); V via ldmatrix.trans ----
        #pragma unroll
        for (int jn = 0; jn < 8; jn++) {
            #pragma unroll
            for (int kc = 0; kc < 4; kc++) {
                int vrow = kc * 16 + (lane & 15);
                uint32_t vh0, vh1;
                ldsm_x2t(vh0, vh1, smem_u32(&VH[st][vrow][jn * 8]));
                mma_f16(O[jn], ph[kc][0], ph[kc][1], ph[kc][2], ph[kc][3], vh0, vh1);
            }
        }
        __syncthreads();

        if (kt + 2 < 16) issue_kv(kt + 2, st);
    }

    // ---- normalize + write single fp16 ----
    float inv0 = l0 > 0.0f ? 1.0f / l0 : 0.0f;
    float inv1 = l1 > 0.0f ? 1.0f / l1 : 0.0f;
    int row0 = grow0 + warp * 16 + (lane >> 2);
    int col  = ghc + ((lane & 3) << 1);
    #pragma unroll
    for (int jn = 0; jn < 8; jn++) {
        *reinterpret_cast<uint32_t*>(Oh + (size_t)row0 * D_ + col + jn * 8) =
            pack_h(__float2half_rn(O[jn][0] * inv0), __float2half_rn(O[jn][1] * inv0));
        *reinterpret_cast<uint32_t*>(Oh + (size_t)(row0 + 8) * D_ + col + jn * 8) =
            pack_h(__float2half_rn(O[jn][2] * inv1), __float2half_rn(O[jn][3] * inv1));
    }
}

// ---------------------------------------------------------------------------
// Launch
// ---------------------------------------------------------------------------
extern "C" void kernel_launch(void* const* d_in, const int* in_sizes, int n_in,
                              void* d_out, int out_size)
{
    const float* query = (const float*)d_in[0];
    const float* key   = (const float*)d_in[1];
    const float* value = (const float*)d_in[2];
    const int*   mask  = (const int*)d_in[3];
    const float* Wq = (const float*)d_in[4];
    const float* bq = (const float*)d_in[5];
    const float* Wk = (const float*)d_in[6];
    const float* bk = (const float*)d_in[7];
    const float* Wv = (const float*)d_in[8];
    const float* bv = (const float*)d_in[9];
    const float* Wo = (const float*)d_in[10];
    const float* bo = (const float*)d_in[11];
    float* out = (float*)d_out;

    void *p[15];
    cudaGetSymbolAddress(&p[0],  g_Iqh);  cudaGetSymbolAddress(&p[1],  g_Iql);
    cudaGetSymbolAddress(&p[2],  g_Ikh);  cudaGetSymbolAddress(&p[3],  g_Ikl);
    cudaGetSymbolAddress(&p[4],  g_Ivh);  cudaGetSymbolAddress(&p[5],  g_Ivl);
    cudaGetSymbolAddress(&p[6],  g_Wq16); cudaGetSymbolAddress(&p[7],  g_Wk16);
    cudaGetSymbolAddress(&p[8],  g_Wv16); cudaGetSymbolAddress(&p[9],  g_Wo16);
    cudaGetSymbolAddress(&p[10], g_Qhi);  cudaGetSymbolAddress(&p[11], g_Qlo);
    cudaGetSymbolAddress(&p[12], g_Khi);  cudaGetSymbolAddress(&p[13], g_Vhi);
    cudaGetSymbolAddress(&p[14], g_Athi);
    __half* Iqh = (__half*)p[0];  __half* Iql = (__half*)p[1];
    __half* Ikh = (__half*)p[2];  __half* Ikl = (__half*)p[3];
    __half* Ivh = (__half*)p[4];  __half* Ivl = (__half*)p[5];
    __half* Wq16 = (__half*)p[6]; __half* Wk16 = (__half*)p[7];
    __half* Wv16 = (__half*)p[8]; __half* Wo16 = (__half*)p[9];
    __half* Qhi = (__half*)p[10]; __half* Qlo = (__half*)p[11];
    __half* Khi = (__half*)p[12]; __half* Vhi = (__half*)p[13];
    __half* Athi = (__half*)p[14];

    cudaFuncSetAttribute(gemm_f16_multi,
                         cudaFuncAttributeMaxDynamicSharedMemorySize, GSMEM);

    prep_kernel<<<dim3(512, 1, 7), 256>>>(
        query, key, value, Wq, Wk, Wv, Wo,
        Iqh, Iql, Ikh, Ikl, Ivh, Ivl, Wq16, Wk16, Wv16, Wo16);

    GemmArgs qa = { Iqh, Iql, Wq16, bq, nullptr, Qhi, Qlo, 1, 0.125f };
    GemmArgs ka = { Ikh, Ikl, Wk16, bk, nullptr, Khi, nullptr, 1, 1.0f };
    GemmArgs va = { Ivh, Ivl, Wv16, bv, nullptr, Vhi, nullptr, 1, 1.0f };
    GemmArgs oa = { Athi, nullptr, Wo16, bo, out, nullptr, nullptr, 0, 1.0f };

    gemm_f16_multi<<<dim3(D_ / 128, M_TOT / 128, 3), 256, GSMEM>>>(qa, ka, va);

    flash_hmma_kernel<<<dim3(L_ / 128, H_, B_), 256>>>(
        Qhi, Qlo, Khi, Vhi, mask, Athi);

    gemm_f16_multi<<<dim3(D_ / 128, M_TOT / 128, 1), 256, GSMEM>>>(oa, oa, oa);
}

// round 13
// speedup vs baseline: 5.2672x; 1.3331x over previous
#include <cuda_runtime.h>
#include <cuda_fp16.h>
#include <cstdint>

#define B_   4
#define L_   1024
#define D_   1024
#define H_   16
#define HD_  64
#define M_TOT (B_ * L_)   // 4096

// Scratch (static device globals — allocation-guard safe)
__device__ __half g_Iqh[M_TOT * D_], g_Iql[M_TOT * D_];   // query input split (2-term)
__device__ __half g_Ikh[M_TOT * D_];                      // key input (1-term)
__device__ __half g_Ivh[M_TOT * D_];                      // value input (1-term)
__device__ __half g_Wq16[D_ * D_], g_Wk16[D_ * D_], g_Wv16[D_ * D_], g_Wo16[D_ * D_];
__device__ __half g_Qhi[M_TOT * D_];                      // Q projected (single fp16, pre-scaled 1/8)
__device__ __half g_Khi[M_TOT * D_], g_Vhi[M_TOT * D_];
__device__ __half g_Athi[M_TOT * D_];                     // attention out (single fp16)

// ===========================================================================
// Helpers
// ===========================================================================
__device__ __forceinline__ uint32_t smem_u32(const void* p) {
    uint32_t a;
    asm("{ .reg .u64 t; cvta.to.shared.u64 t, %1; cvt.u32.u64 %0, t; }" : "=r"(a) : "l"(p));
    return a;
}
__device__ __forceinline__ void ldsm_x4(uint32_t& r0, uint32_t& r1, uint32_t& r2, uint32_t& r3, uint32_t a) {
    asm volatile("ldmatrix.sync.aligned.m8n8.x4.shared.b16 {%0,%1,%2,%3}, [%4];"
                 : "=r"(r0), "=r"(r1), "=r"(r2), "=r"(r3) : "r"(a));
}
__device__ __forceinline__ void ldsm_x2(uint32_t& r0, uint32_t& r1, uint32_t a) {
    asm volatile("ldmatrix.sync.aligned.m8n8.x2.shared.b16 {%0,%1}, [%2];"
                 : "=r"(r0), "=r"(r1) : "r"(a));
}
__device__ __forceinline__ void ldsm_x2t(uint32_t& r0, uint32_t& r1, uint32_t a) {
    asm volatile("ldmatrix.sync.aligned.m8n8.x2.trans.shared.b16 {%0,%1}, [%2];"
                 : "=r"(r0), "=r"(r1) : "r"(a));
}
__device__ __forceinline__ void mma_f16(float* c,
    uint32_t a0, uint32_t a1, uint32_t a2, uint32_t a3, uint32_t b0, uint32_t b1) {
    asm volatile("mma.sync.aligned.m16n8k16.row.col.f32.f16.f16.f32 "
                 "{%0,%1,%2,%3}, {%4,%5,%6,%7}, {%8,%9}, {%0,%1,%2,%3};"
                 : "+f"(c[0]), "+f"(c[1]), "+f"(c[2]), "+f"(c[3])
                 : "r"(a0), "r"(a1), "r"(a2), "r"(a3), "r"(b0), "r"(b1));
}
__device__ __forceinline__ uint32_t pack_h(__half lo, __half hi) {
    return ((uint32_t)__half_as_ushort(hi) << 16) | __half_as_ushort(lo);
}
__device__ __forceinline__ void split2h(float x, __half& h, __half& l) {
    h = __float2half_rn(x);
    l = __float2half_rn(x - __half2float(h));
}
__device__ __forceinline__ void cp16(uint32_t dst, const void* src) {
    asm volatile("cp.async.cg.shared.global [%0], [%1], 16;" :: "r"(dst), "l"(src));
}
__device__ __forceinline__ void cp_commit() { asm volatile("cp.async.commit_group;"); }
template<int N> __device__ __forceinline__ void cp_wait() {
    asm volatile("cp.async.wait_group %0;" :: "n"(N));
}

// ===========================================================================
// Prep: query -> hi/lo split; key/value/weights -> single fp16.  grid (512,1,7)
// ===========================================================================
__global__ __launch_bounds__(256) void prep_kernel(
    const float* __restrict__ q, const float* __restrict__ k, const float* __restrict__ v,
    const float* __restrict__ wq, const float* __restrict__ wk,
    const float* __restrict__ wv, const float* __restrict__ wo,
    __half* qh, __half* ql, __half* kh, __half* vh,
    __half* wqh, __half* wkh, __half* wvh, __half* woh)
{
    const int z = blockIdx.z;
    const int base = blockIdx.x * 256 + threadIdx.x;
    if (z == 0) {
        // query: 2-term split
        #pragma unroll
        for (int i = 0; i < 8; i++) {
            int e4 = base + i * 131072;
            float4 x = reinterpret_cast<const float4*>(q)[e4];
            __half h0, h1, h2, h3, l0, l1, l2, l3;
            split2h(x.x, h0, l0); split2h(x.y, h1, l1);
            split2h(x.z, h2, l2); split2h(x.w, h3, l3);
            uint2 hv = { pack_h(h0, h1), pack_h(h2, h3) };
            uint2 lv = { pack_h(l0, l1), pack_h(l2, l3) };
            *reinterpret_cast<uint2*>(qh + (size_t)e4 * 4) = hv;
            *reinterpret_cast<uint2*>(ql + (size_t)e4 * 4) = lv;
        }
    } else if (z < 3) {
        const float* src = (z == 1) ? k : v;
        __half* dst = (z == 1) ? kh : vh;
        #pragma unroll
        for (int i = 0; i < 8; i++) {
            int e4 = base + i * 131072;
            float4 x = reinterpret_cast<const float4*>(src)[e4];
            uint2 hv = { pack_h(__float2half_rn(x.x), __float2half_rn(x.y)),
                         pack_h(__float2half_rn(x.z), __float2half_rn(x.w)) };
            *reinterpret_cast<uint2*>(dst + (size_t)e4 * 4) = hv;
        }
    } else {
        const float* src = (z == 3) ? wq : (z == 4) ? wk : (z == 5) ? wv : wo;
        __half* dst = (z == 3) ? wqh : (z == 4) ? wkh : (z == 5) ? wvh : woh;
        #pragma unroll
        for (int i = 0; i < 2; i++) {
            int e4 = base + i * 131072;
            float4 x = reinterpret_cast<const float4*>(src)[e4];
            uint2 wv2 = { pack_h(__float2half_rn(x.x), __float2half_rn(x.y)),
                          pack_h(__float2half_rn(x.z), __float2half_rn(x.w)) };
            *reinterpret_cast<uint2*>(dst + (size_t)e4 * 4) = wv2;
        }
    }
}

// ===========================================================================
// fp16 HMMA GEMM, cp.async double-buffered. A-side 1- or 2-term (two_term flag).
//   C = (Ah [+ Al]) @ Wh^T + bias, then * oscale.
// ===========================================================================
#define BKC   32
#define NCH   (D_ / BKC)   // 32
#define SST   40
#define ARR_H (128 * SST)
#define STG_H (3 * ARR_H)
#define GSMEM (2 * STG_H * 2)          // 61440 bytes

struct GemmArgs {
    const __half* Ah;
    const __half* Al;
    const __half* Wh;
    const float*  bias;
    float*  C;
    __half* Chi;
    __half* Clo;
    int     two_term;   // A-side lo term present
    float   oscale;     // output scale (applied after bias)
};

__device__ __forceinline__ void issue_chunk(
    const GemmArgs& g, int m0, int n0, int k0, int t, uint32_t stage_b)
{
    #pragma unroll
    for (int i = 0; i < 2; i++) {
        int s  = t + (i << 8);
        int r  = s >> 2;
        int c8 = (s & 3) << 3;
        uint32_t d = stage_b + (uint32_t)(r * SST + c8) * 2;
        size_t goff = (size_t)(m0 + r) * D_ + k0 + c8;
        cp16(d, g.Ah + goff);
        if (g.two_term) cp16(d + ARR_H * 2, g.Al + goff);
        cp16(d + 2 * ARR_H * 2, g.Wh + (size_t)(n0 + r) * D_ + k0 + c8);
    }
}

__global__ __launch_bounds__(256, 2) void gemm_f16_multi(
    GemmArgs ga0, GemmArgs ga1, GemmArgs ga2)
{
    extern __shared__ __half dsm[];
    const GemmArgs g = (blockIdx.z == 0) ? ga0 : ((blockIdx.z == 1) ? ga1 : ga2);

    const int t    = threadIdx.x;
    const int lane = t & 31;
    const int warp = t >> 5;
    const int wm   = warp >> 2;
    const int wn   = warp & 3;
    const int m0   = blockIdx.y * 128;
    const int n0   = blockIdx.x * 128;
    const uint32_t sb = smem_u32(dsm);

    float acc[4][4][4];
    #pragma unroll
    for (int i = 0; i < 4; i++)
        #pragma unroll
        for (int j = 0; j < 4; j++)
            #pragma unroll
            for (int r = 0; r < 4; r++) acc[i][j][r] = 0.0f;

    issue_chunk(g, m0, n0, 0, t, sb);
    cp_commit();
    issue_chunk(g, m0, n0, BKC, t, sb + STG_H * 2);
    cp_commit();

    for (int ck = 0; ck < NCH; ck++) {
        const int st = ck & 1;
        const __half* cah = dsm + st * STG_H;
        const __half* cal = cah + ARR_H;
        const __half* cbh = cah + 2 * ARR_H;

        if (ck + 1 < NCH) cp_wait<1>(); else cp_wait<0>();
        __syncthreads();

        #pragma unroll
        for (int ks = 0; ks < 2; ks++) {
            const int k0 = ks * 16;
            uint32_t bh[4][2];
            #pragma unroll
            for (int j = 0; j < 4; j++) {
                int row = wn * 32 + j * 8 + (lane & 7);
                int col = k0 + (((lane >> 3) & 1) << 3);
                ldsm_x2(bh[j][0], bh[j][1], smem_u32(cbh + row * SST + col));
            }
            #pragma unroll
            for (int i = 0; i < 4; i++) {
                int row = wm * 64 + i * 16 + (lane & 15);
                int col = k0 + ((lane >> 4) << 3);
                uint32_t ah0, ah1, ah2, ah3;
                ldsm_x4(ah0, ah1, ah2, ah3, smem_u32(cah + row * SST + col));
                #pragma unroll
                for (int j = 0; j < 4; j++)
                    mma_f16(acc[i][j], ah0, ah1, ah2, ah3, bh[j][0], bh[j][1]);
                if (g.two_term) {
                    uint32_t al0, al1, al2, al3;
                    ldsm_x4(al0, al1, al2, al3, smem_u32(cal + row * SST + col));
                    #pragma unroll
                    for (int j = 0; j < 4; j++)
                        mma_f16(acc[i][j], al0, al1, al2, al3, bh[j][0], bh[j][1]);
                }
            }
        }
        __syncthreads();

        if (ck + 2 < NCH) {
            issue_chunk(g, m0, n0, (ck + 2) * BKC, t, sb + st * STG_H * 2);
            cp_commit();
        }
    }

    const int lr = lane >> 2;
    const int lc = (lane & 3) << 1;
    #pragma unroll
    for (int i = 0; i < 4; i++) {
        #pragma unroll
        for (int j = 0; j < 4; j++) {
            int row = m0 + wm * 64 + i * 16 + lr;
            int col = n0 + wn * 32 + j * 8 + lc;
            float2 bz = *reinterpret_cast<const float2*>(g.bias + col);
            float v0 = (acc[i][j][0] + bz.x) * g.oscale;
            float v1 = (acc[i][j][1] + bz.y) * g.oscale;
            float v2 = (acc[i][j][2] + bz.x) * g.oscale;
            float v3 = (acc[i][j][3] + bz.y) * g.oscale;
            if (g.Chi) {
                if (g.Clo) {
                    __half h0, h1, h2, h3, l0, l1, l2, l3;
                    split2h(v0, h0, l0); split2h(v1, h1, l1);
                    split2h(v2, h2, l2); split2h(v3, h3, l3);
                    *reinterpret_cast<uint32_t*>(g.Chi + (size_t)row * D_ + col)       = pack_h(h0, h1);
                    *reinterpret_cast<uint32_t*>(g.Clo + (size_t)row * D_ + col)       = pack_h(l0, l1);
                    *reinterpret_cast<uint32_t*>(g.Chi + (size_t)(row + 8) * D_ + col) = pack_h(h2, h3);
                    *reinterpret_cast<uint32_t*>(g.Clo + (size_t)(row + 8) * D_ + col) = pack_h(l2, l3);
                } else {
                    *reinterpret_cast<uint32_t*>(g.Chi + (size_t)row * D_ + col) =
                        pack_h(__float2half_rn(v0), __float2half_rn(v1));
                    *reinterpret_cast<uint32_t*>(g.Chi + (size_t)(row + 8) * D_ + col) =
                        pack_h(__float2half_rn(v2), __float2half_rn(v3));
                }
            } else {
                float2 o0 = { v0, v1 }, o1 = { v2, v3 };
                *reinterpret_cast<float2*>(g.C + (size_t)row * D_ + col) = o0;
                *reinterpret_cast<float2*>(g.C + (size_t)(row + 8) * D_ + col) = o1;
            }
        }
    }
}

// ===========================================================================
// HMMA flash attention: Q/K/V/P/At all single fp16 (Q pre-scaled by 1/8).
//   S = Q*K ; P = fp16(softmax) ; O += P*V ; At = fp16(O/l)
// ===========================================================================
#define FST 72

__global__ __launch_bounds__(256) void flash_hmma_kernel(
    const __half* __restrict__ Qhi,
    const __half* __restrict__ Khi, const __half* __restrict__ Vhi,
    const int* __restrict__ mask,
    __half* __restrict__ Oh)
{
    __shared__ __align__(16) __half KH[2][64][FST];
    __shared__ __align__(16) __half VH[2][64][FST];
    __shared__ int MI[2][64];

    const int t    = threadIdx.x;
    const int lane = t & 31;
    const int warp = t >> 5;
    const int qt   = blockIdx.x;
    const int h    = blockIdx.y;
    const int b    = blockIdx.z;
    const int grow0 = b * L_ + qt * 128;
    const int ghc   = h * HD_;

    // ---- stage Q tile (128 rows, hi only) through KH[0]|VH[0] ----
    #pragma unroll
    for (int i = 0; i < 2; i++) {
        int v = t + i * 256;       // 0..511
        int r = v >> 2;            // 0..127
        int c = (v & 3) << 4;      // 0,16,32,48
        __half* dh = (r < 64) ? &KH[0][r][c] : &VH[0][r - 64][c];
        *reinterpret_cast<uint4*>(dh) =
            *reinterpret_cast<const uint4*>(Qhi + (size_t)(grow0 + r) * D_ + ghc + c);
        *reinterpret_cast<uint4*>(dh + 8) =
            *reinterpret_cast<const uint4*>(Qhi + (size_t)(grow0 + r) * D_ + ghc + c + 8);
    }
    __syncthreads();

    uint32_t qh[4][4];
    {
        int ar = warp * 16 + (lane & 15);
        int ac = (lane >> 4) << 3;
        const __half* sh = (ar < 64) ? &KH[0][ar][0] : &VH[0][ar - 64][0];
        #pragma unroll
        for (int kc = 0; kc < 4; kc++)
            ldsm_x4(qh[kc][0], qh[kc][1], qh[kc][2], qh[kc][3], smem_u32(sh + kc * 16 + ac));
    }
    __syncthreads();   // Q fragments read; smem stages free for K/V

    float O[8][4];
    #pragma unroll
    for (int j = 0; j < 8; j++)
        #pragma unroll
        for (int r = 0; r < 4; r++) O[j][r] = 0.0f;
    float m0 = -1e30f, m1 = -1e30f, l0 = 0.0f, l1 = 0.0f;

    auto issue_kv = [&](int tile, int st) {
        const int krow0 = b * L_ + tile * 64;
        #pragma unroll
        for (int i = 0; i < 2; i++) {
            int s = t + i * 256;
            int r = s >> 3;
            int c = (s & 7) << 3;
            size_t gb = (size_t)(krow0 + r) * D_ + ghc + c;
            cp16(smem_u32(&KH[st][r][c]), Khi + gb);
            cp16(smem_u32(&VH[st][r][c]), Vhi + gb);
        }
        if (t < 16) cp16(smem_u32(&MI[st][t * 4]), mask + b * L_ + tile * 64 + t * 4);
        cp_commit();
    };

    issue_kv(0, 0);
    issue_kv(1, 1);

    for (int kt = 0; kt < 16; kt++) {
        const int st = kt & 1;
        if (kt + 1 < 16) cp_wait<1>(); else cp_wait<0>();
        __syncthreads();

        // ---- S = Q K^T (single term, Q pre-scaled) ----
        float S[8][4];
        #pragma unroll
        for (int j = 0; j < 8; j++) {
            S[j][0] = S[j][1] = S[j][2] = S[j][3] = 0.0f;
            int brow = j * 8 + (lane & 7);
            #pragma unroll
            for (int kc = 0; kc < 4; kc++) {
                int bcol = kc * 16 + (((lane >> 3) & 1) << 3);
                uint32_t bh0, bh1;
                ldsm_x2(bh0, bh1, smem_u32(&KH[st][brow][bcol]));
                mma_f16(S[j], qh[kc][0], qh[kc][1], qh[kc][2], qh[kc][3], bh0, bh1);
            }
        }

        // ---- softmax ----
        float rmax0 = -3.0e38f, rmax1 = -3.0e38f;
        #pragma unroll
        for (int j = 0; j < 8; j++) {
            int cidx = j * 8 + ((lane & 3) << 1);
            float ma = MI[st][cidx]     ? -1e30f : 0.0f;
            float mb = MI[st][cidx + 1] ? -1e30f : 0.0f;
            S[j][0] += ma; S[j][1] += mb; S[j][2] += ma; S[j][3] += mb;
            rmax0 = fmaxf(rmax0, fmaxf(S[j][0], S[j][1]));
            rmax1 = fmaxf(rmax1, fmaxf(S[j][2], S[j][3]));
        }
        rmax0 = fmaxf(rmax0, __shfl_xor_sync(0xffffffffu, rmax0, 1));
        rmax0 = fmaxf(rmax0, __shfl_xor_sync(0xffffffffu, rmax0, 2));
        rmax1 = fmaxf(rmax1, __shfl_xor_sync(0xffffffffu, rmax1, 1));
        rmax1 = fmaxf(rmax1, __shfl_xor_sync(0xffffffffu, rmax1, 2));

        float mn0 = fmaxf(m0, rmax0), mn1 = fmaxf(m1, rmax1);
        float a0 = __expf(m0 - mn0), a1 = __expf(m1 - mn1);
        m0 = mn0; m1 = mn1;

        float sum0 = 0.0f, sum1 = 0.0f;
        #pragma unroll
        for (int j = 0; j < 8; j++) {
            S[j][0] = __expf(S[j][0] - mn0); sum0 += S[j][0];
            S[j][1] = __expf(S[j][1] - mn0); sum0 += S[j][1];
            S[j][2] = __expf(S[j][2] - mn1); sum1 += S[j][2];
            S[j][3] = __expf(S[j][3] - mn1); sum1 += S[j][3];
        }
        sum0 += __shfl_xor_sync(0xffffffffu, sum0, 1);
        sum0 += __shfl_xor_sync(0xffffffffu, sum0, 2);
        sum1 += __shfl_xor_sync(0xffffffffu, sum1, 1);
        sum1 += __shfl_xor_sync(0xffffffffu, sum1, 2);
        l0 = l0 * a0 + sum0;
        l1 = l1 * a1 + sum1;

        #pragma unroll
        for (int j = 0; j < 8; j++) {
            O[j][0] *= a0; O[j][1] *= a0; O[j][2] *= a1; O[j][3] *= a1;
        }

        // ---- P -> single fp16 A-fragments ----
        uint32_t ph[4][4];
        #pragma unroll
        for (int kc = 0; kc < 4; kc++) {
            const float* x = S[2 * kc];
            const float* y = S[2 * kc + 1];
            ph[kc][0] = pack_h(__float2half_rn(x[0]), __float2half_rn(x[1]));
            ph[kc][1] = pack_h(__float2half_rn(x[2]), __float2half_rn(x[3]));
            ph[kc][2] = pack_h(__float2half_rn(y[0]), __float2half_rn(y[1]));
            ph[kc][3] = pack_h(__float2half_rn(y[2]), __float2half_rn(y[3]));
        }

        // ---- O += P V (single term); V via ldmatrix.trans ----
        #pragma unroll
        for (int jn = 0; jn < 8; jn++) {
            #pragma unroll
            for (int kc = 0; kc < 4; kc++) {
                int vrow = kc * 16 + (lane & 15);
                uint32_t vh0, vh1;
                ldsm_x2t(vh0, vh1, smem_u32(&VH[st][vrow][jn * 8]));
                mma_f16(O[jn], ph[kc][0], ph[kc][1], ph[kc][2], ph[kc][3], vh0, vh1);
            }
        }
        __syncthreads();

        if (kt + 2 < 16) issue_kv(kt + 2, st);
    }

    // ---- normalize + write single fp16 ----
    float inv0 = l0 > 0.0f ? 1.0f / l0 : 0.0f;
    float inv1 = l1 > 0.0f ? 1.0f / l1 : 0.0f;
    int row0 = grow0 + warp * 16 + (lane >> 2);
    int col  = ghc + ((lane & 3) << 1);
    #pragma unroll
    for (int jn = 0; jn < 8; jn++) {
        *reinterpret_cast<uint32_t*>(Oh + (size_t)row0 * D_ + col + jn * 8) =
            pack_h(__float2half_rn(O[jn][0] * inv0), __float2half_rn(O[jn][1] * inv0));
        *reinterpret_cast<uint32_t*>(Oh + (size_t)(row0 + 8) * D_ + col + jn * 8) =
            pack_h(__float2half_rn(O[jn][2] * inv1), __float2half_rn(O[jn][3] * inv1));
    }
}

// ---------------------------------------------------------------------------
// Launch
// ---------------------------------------------------------------------------
extern "C" void kernel_launch(void* const* d_in, const int* in_sizes, int n_in,
                              void* d_out, int out_size)
{
    const float* query = (const float*)d_in[0];
    const float* key   = (const float*)d_in[1];
    const float* value = (const float*)d_in[2];
    const int*   mask  = (const int*)d_in[3];
    const float* Wq = (const float*)d_in[4];
    const float* bq = (const float*)d_in[5];
    const float* Wk = (const float*)d_in[6];
    const float* bk = (const float*)d_in[7];
    const float* Wv = (const float*)d_in[8];
    const float* bv = (const float*)d_in[9];
    const float* Wo = (const float*)d_in[10];
    const float* bo = (const float*)d_in[11];
    float* out = (float*)d_out;

    void *p[13];
    cudaGetSymbolAddress(&p[0],  g_Iqh);  cudaGetSymbolAddress(&p[1],  g_Iql);
    cudaGetSymbolAddress(&p[2],  g_Ikh);  cudaGetSymbolAddress(&p[3],  g_Ivh);
    cudaGetSymbolAddress(&p[4],  g_Wq16); cudaGetSymbolAddress(&p[5],  g_Wk16);
    cudaGetSymbolAddress(&p[6],  g_Wv16); cudaGetSymbolAddress(&p[7],  g_Wo16);
    cudaGetSymbolAddress(&p[8],  g_Qhi);
    cudaGetSymbolAddress(&p[9],  g_Khi);  cudaGetSymbolAddress(&p[10], g_Vhi);
    cudaGetSymbolAddress(&p[11], g_Athi);
    __half* Iqh = (__half*)p[0];  __half* Iql = (__half*)p[1];
    __half* Ikh = (__half*)p[2];  __half* Ivh = (__half*)p[3];
    __half* Wq16 = (__half*)p[4]; __half* Wk16 = (__half*)p[5];
    __half* Wv16 = (__half*)p[6]; __half* Wo16 = (__half*)p[7];
    __half* Qhi = (__half*)p[8];
    __half* Khi = (__half*)p[9];  __half* Vhi = (__half*)p[10];
    __half* Athi = (__half*)p[11];

    cudaFuncSetAttribute(gemm_f16_multi,
                         cudaFuncAttributeMaxDynamicSharedMemorySize, GSMEM);

    prep_kernel<<<dim3(512, 1, 7), 256>>>(
        query, key, value, Wq, Wk, Wv, Wo,
        Iqh, Iql, Ikh, Ivh, Wq16, Wk16, Wv16, Wo16);

    GemmArgs qa = { Iqh, Iql, Wq16, bq, nullptr, Qhi, nullptr, 1, 0.125f };
    GemmArgs ka = { Ikh, nullptr, Wk16, bk, nullptr, Khi, nullptr, 0, 1.0f };
    GemmArgs va = { Ivh, nullptr, Wv16, bv, nullptr, Vhi, nullptr, 0, 1.0f };
    GemmArgs oa = { Athi, nullptr, Wo16, bo, out, nullptr, nullptr, 0, 1.0f };

    gemm_f16_multi<<<dim3(D_ / 128, M_TOT / 128, 3), 256, GSMEM>>>(qa, ka, va);

    flash_hmma_kernel<<<dim3(L_ / 128, H_, B_), 256>>>(
        Qhi, Khi, Vhi, mask, Athi);

    gemm_f16_multi<<<dim3(D_ / 128, M_TOT / 128, 1), 256, GSMEM>>>(oa, oa, oa);
}